// round 11
// baseline (speedup 1.0000x reference)
#include <cuda_runtime.h>
#include <cuda_fp16.h>
#include <math.h>
#include <stdint.h>

// Problem constants
#define BB 8
#define DD 512
#define SS 4096
#define FF 2048

// ---------------- static scratch (no allocations allowed) ----------------
// fp32
__device__ float g_y [(size_t)BB * SS * DD];
__device__ float g_h2[(size_t)BB * SS * DD];
__device__ double g_acc[32];
// fp16 operands (row-major [x][k] for every GEMM)
__device__ __half g_xh  [(size_t)BB * SS * DD];   // x^T  [B,S,D]
__device__ __half g_qh  [(size_t)BB * SS * DD];
__device__ __half g_kh  [(size_t)BB * SS * DD];
__device__ __half g_vt  [(size_t)BB * DD * SS];   // v'^T [B,D,S]  (v' = x^T Wv Wo)
__device__ __half g_sh  [(size_t)BB * SS * SS];   // scores/attn fp16
__device__ __half g_yh  [(size_t)BB * SS * DD];   // normalized post, fp16 copy
__device__ __half g_h1h [(size_t)BB * SS * FF];
__device__ __half g_wqT [DD * DD];
__device__ __half g_wkT [DD * DD];
__device__ __half g_wvh [DD * DD];                // Wv fp16, NOT transposed
__device__ __half g_woT [DD * DD];
__device__ __half g_wvoT[DD * DD];                // (Wv@Wo)^T fp16
__device__ __half g_w1T [(size_t)DD * FF];        // [F,D]
__device__ __half g_w2T [(size_t)DD * FF];        // [D,F]

// ---------------- helpers ----------------
__device__ __forceinline__ uint32_t smem_u32(const void* p)
{
    uint32_t a;
    asm("{ .reg .u64 t; cvta.to.shared.u64 t, %1; cvt.u32.u64 %0, t; }" : "=r"(a) : "l"(p));
    return a;
}

#define CP16(d, s) asm volatile("cp.async.ca.shared.global [%0], [%1], 16;" :: "r"(d), "l"(s))
#define CPC()  asm volatile("cp.async.commit_group;" ::: "memory")
#define CPW0() asm volatile("cp.async.wait_group 0;" ::: "memory")
#define CPW1() asm volatile("cp.async.wait_group 1;" ::: "memory")

#define LDMX4(r, addr) \
    asm volatile("ldmatrix.sync.aligned.m8n8.x4.shared.b16 {%0,%1,%2,%3}, [%4];" \
        : "=r"((r)[0]), "=r"((r)[1]), "=r"((r)[2]), "=r"((r)[3]) : "r"(addr))

__device__ __forceinline__ void mma16816(float c[4], const uint32_t a[4],
                                         uint32_t b0, uint32_t b1)
{
    asm volatile(
        "mma.sync.aligned.m16n8k16.row.col.f32.f16.f16.f32 "
        "{%0,%1,%2,%3}, {%4,%5,%6,%7}, {%8,%9}, {%0,%1,%2,%3};\n"
        : "+f"(c[0]), "+f"(c[1]), "+f"(c[2]), "+f"(c[3])
        : "r"(a[0]), "r"(a[1]), "r"(a[2]), "r"(a[3]),
          "r"(b0), "r"(b1));
}

// ---------------- fp16 tensor-core GEMM, 2-stage cp.async + ldmatrix ----------------
// CTA tile 128 x BN (BN = 128 or 256), BN threads, warps of 64x64 tiles (2 x BN/64).
// C[M,N] = A[M,K] * B[N,K]^T, A/B fp16 row-major. TK=64.
// EPI: 0 none, 1 +bias, 2 relu(+bias),
//      3 +residual from res[N,M]-layout (x^T, ld=SS) + stats -> fp32 out
//      4 +bias +residual from res[M,N]-layout (ld=DD) + stats -> fp32 out
// OUT: 0 fp32 [M,N]; 1 fp16 [M,N]; 2 fp16 transposed [N,M]
#define SKB 144                      // smem row stride in bytes
#define TILE_A (128 * SKB)           // 18432 bytes

template <int EPI, int OUT, int BN>
__global__ __launch_bounds__(BN)
void gemm_h(const __half* __restrict__ A, const __half* __restrict__ B,
            const float* __restrict__ bias, void* __restrict__ Cv,
            int K, int lda, int ldb, int ldc,
            long long sA, long long sB, long long sC,
            const float* __restrict__ res, long long sR, double* __restrict__ stats)
{
    constexpr int NT = BN;                  // threads
    constexpr int TILE_BSZ = BN * SKB;      // B tile bytes per stage
    constexpr int RPT_A = 1024 / NT;        // A 16B-chunk iters per thread
    constexpr int RSTEP = NT / 8;           // row step per staging iter

    extern __shared__ char smem[];
    const uint32_t base = smem_u32(smem);
    const uint32_t bBase = base + 2 * TILE_A;

    const int bz = blockIdx.z;
    const __half* Ab = A + (long long)bz * sA;
    const __half* Bb = B + (long long)bz * sB;

    const int m0 = blockIdx.y * 128;
    const int n0 = blockIdx.x * BN;
    const int tid  = threadIdx.x;
    const int lane = tid & 31;
    const int warp = tid >> 5;
    const int wm = (warp & 1) * 64;         // 2 warp rows
    const int wn = (warp >> 1) * 64;        // BN/64 warp cols
    const int qr = lane >> 2;   // 0..7
    const int qc = lane & 3;    // 0..3

    float acc[4][8][4];
#pragma unroll
    for (int i = 0; i < 4; i++)
#pragma unroll
        for (int j = 0; j < 8; j++)
#pragma unroll
            for (int q = 0; q < 4; q++) acc[i][j][q] = 0.f;

    const int NKB = K >> 6;

    const int sx = tid >> 3;       // staging row base
    const int sc = tid & 7;        // 16B chunk in row
    const uint32_t sdst = (uint32_t)(sx * SKB + sc * 16);

#define STAGE(buf, k0)                                                          \
    do {                                                                        \
        const uint32_t aD = base + (buf) * TILE_A + sdst;                       \
        const uint32_t bD = bBase + (buf) * TILE_BSZ + sdst;                    \
        const __half* aSrc = Ab + (long long)(m0 + sx) * lda + (k0) + sc * 8;   \
        const __half* bSrc = Bb + (long long)(n0 + sx) * ldb + (k0) + sc * 8;   \
        _Pragma("unroll")                                                       \
        for (int it = 0; it < RPT_A; it++)                                      \
            CP16(aD + it * (RSTEP * SKB), aSrc + (long long)(it * RSTEP) * lda);\
        _Pragma("unroll")                                                       \
        for (int it = 0; it < 8; it++)                                          \
            CP16(bD + it * (RSTEP * SKB), bSrc + (long long)(it * RSTEP) * ldb);\
    } while (0)

    STAGE(0, 0);
    CPC();

    // per-lane ldmatrix offsets: lanes 0-15 -> rows (x&15) @ +0B, 16-31 -> @ +16B
    const uint32_t aOff = (uint32_t)((wm + (lane & 15)) * SKB + (lane >> 4) * 16);
    const uint32_t bOff = (uint32_t)((wn + (lane & 15)) * SKB + (lane >> 4) * 16);

    for (int kb = 0; kb < NKB; kb++) {
        const int cur = kb & 1;
        if (kb + 1 < NKB) {
            STAGE(cur ^ 1, (kb + 1) << 6);
            CPC();
            CPW1();
        } else {
            CPW0();
        }
        __syncthreads();

        const uint32_t aT = base + cur * TILE_A + aOff;
        const uint32_t bT = bBase + cur * TILE_BSZ + bOff;
#pragma unroll
        for (int ks = 0; ks < 4; ks++) {
            uint32_t af[4][4], bq[4][4];
#pragma unroll
            for (int mi = 0; mi < 4; mi++)
                LDMX4(af[mi], aT + mi * (16 * SKB) + ks * 32);
#pragma unroll
            for (int ni = 0; ni < 4; ni++)
                LDMX4(bq[ni], bT + ni * (16 * SKB) + ks * 32);
#pragma unroll
            for (int mi = 0; mi < 4; mi++)
#pragma unroll
                for (int ni = 0; ni < 4; ni++) {
                    mma16816(acc[mi][2 * ni],     af[mi], bq[ni][0], bq[ni][2]);
                    mma16816(acc[mi][2 * ni + 1], af[mi], bq[ni][1], bq[ni][3]);
                }
        }
        __syncthreads();
    }
#undef STAGE

    // ---- epilogue ----
    const float* resb = (EPI >= 3) ? (res + (long long)bz * sR) : nullptr;
    float ls = 0.f, lq = 0.f;

#pragma unroll
    for (int mi = 0; mi < 4; mi++) {
        const int m = m0 + wm + mi * 16 + qr;
#pragma unroll
        for (int ni = 0; ni < 8; ni++) {
            const int nc = n0 + wn + ni * 8 + 2 * qc;
            float c0 = acc[mi][ni][0], c1 = acc[mi][ni][1];
            float c2 = acc[mi][ni][2], c3 = acc[mi][ni][3];
            if (EPI == 1 || EPI == 2 || EPI == 4) {
                const float bx = bias[nc], by = bias[nc + 1];
                c0 += bx; c1 += by; c2 += bx; c3 += by;
            }
            if (EPI == 2) {
                c0 = fmaxf(c0, 0.f); c1 = fmaxf(c1, 0.f);
                c2 = fmaxf(c2, 0.f); c3 = fmaxf(c3, 0.f);
            }
            if (EPI == 3) {
                // residual stored [N, M] (x^T layout, ld = SS)
                c0 += resb[(long long)nc * SS + m];
                c1 += resb[(long long)(nc + 1) * SS + m];
                c2 += resb[(long long)nc * SS + m + 8];
                c3 += resb[(long long)(nc + 1) * SS + m + 8];
            }
            if (EPI == 4) {
                // residual stored [M, N] (ld = DD)
                const float2 r0 = *(const float2*)(resb + (long long)m * DD + nc);
                const float2 r1 = *(const float2*)(resb + (long long)(m + 8) * DD + nc);
                c0 += r0.x; c1 += r0.y; c2 += r1.x; c3 += r1.y;
            }
            if (EPI >= 3) {
                ls += c0 + c1 + c2 + c3;
                lq += c0 * c0 + c1 * c1 + c2 * c2 + c3 * c3;
            }
            if (OUT == 0) {
                float* C = (float*)Cv + (long long)bz * sC;
                float2 lo; lo.x = c0; lo.y = c1;
                float2 hi; hi.x = c2; hi.y = c3;
                *(float2*)(C + (long long)m * ldc + nc) = lo;
                *(float2*)(C + (long long)(m + 8) * ldc + nc) = hi;
            } else if (OUT == 1) {
                __half* C = (__half*)Cv + (long long)bz * sC;
                *(__half2*)(C + (long long)m * ldc + nc) = __floats2half2_rn(c0, c1);
                *(__half2*)(C + (long long)(m + 8) * ldc + nc) = __floats2half2_rn(c2, c3);
            } else {
                __half* C = (__half*)Cv + (long long)bz * sC;
                C[(long long)nc * ldc + m]           = __float2half_rn(c0);
                C[(long long)(nc + 1) * ldc + m]     = __float2half_rn(c1);
                C[(long long)nc * ldc + m + 8]       = __float2half_rn(c2);
                C[(long long)(nc + 1) * ldc + m + 8] = __float2half_rn(c3);
            }
        }
    }

    if (EPI >= 3) {
        // block-reduce ls/lq into per-batch stats (reuse GEMM smem; mainloop done)
        float* sa = (float*)smem;
        float* sb = sa + NT;
        sa[tid] = ls; sb[tid] = lq;
        __syncthreads();
        for (int o = NT / 2; o > 0; o >>= 1) {
            if (tid < o) { sa[tid] += sa[tid + o]; sb[tid] += sb[tid + o]; }
            __syncthreads();
        }
        if (tid == 0) {
            atomicAdd(stats + 2 * bz + 0, (double)sa[0]);
            atomicAdd(stats + 2 * bz + 1, (double)sb[0]);
        }
    }
}

#define SMEMB128 (2 * TILE_A + 2 * 128 * SKB)   // 73728
#define SMEMB256 (2 * TILE_A + 2 * 256 * SKB)   // 110592

// ---------------- transpose + fp32->fp16 convert: src[R,C] -> dst[C,R] ----------------
__global__ void transpose_h(const float* __restrict__ src, __half* __restrict__ dst,
                            int R, int C)
{
    const int b = blockIdx.z;
    src += (long long)b * R * C;
    dst += (long long)b * R * C;
    const int r0 = blockIdx.y * 32;
    const int c0 = blockIdx.x * 32;
    __shared__ float t[32][33];
    const int tx = threadIdx.x, ty = threadIdx.y;   // 32 x 8
#pragma unroll
    for (int i = 0; i < 32; i += 8)
        t[ty + i][tx] = src[(long long)(r0 + ty + i) * C + c0 + tx];
    __syncthreads();
#pragma unroll
    for (int i = 0; i < 32; i += 8)
        dst[(long long)(c0 + ty + i) * R + r0 + tx] = __float2half_rn(t[tx][ty + i]);
}

// ---------------- straight fp32->fp16 convert ----------------
__global__ void convert_h(const float* __restrict__ src, __half* __restrict__ dst)
{
    const long long i = (long long)blockIdx.x * 256 + threadIdx.x;
    const float4 v = ((const float4*)src)[i];
    __half2* d = (__half2*)dst + i * 2;
    d[0] = __floats2half2_rn(v.x, v.y);
    d[1] = __floats2half2_rn(v.z, v.w);
}

// ---------------- softmax on fp16 scores (in place, scaled) ----------------
__global__ void softmax_h(__half* __restrict__ sh, float scale)
{
    const long long row = blockIdx.x;
    uint4* p = (uint4*)(sh + row * SS);       // 512 uint4 per row (8 halves each)
    const int tid = threadIdx.x;              // 256 threads, 2 uint4 each
    __shared__ float red[256];

    uint4 u[2];
    float f[16];
    u[0] = p[tid];
    u[1] = p[tid + 256];
#pragma unroll
    for (int ii = 0; ii < 2; ii++) {
        const uint32_t* w = (const uint32_t*)&u[ii];
#pragma unroll
        for (int j = 0; j < 4; j++) {
            float2 d = __half22float2(*(const __half2*)&w[j]);
            f[ii * 8 + j * 2]     = d.x;
            f[ii * 8 + j * 2 + 1] = d.y;
        }
    }
    float mx = -INFINITY;
#pragma unroll
    for (int i = 0; i < 16; i++) mx = fmaxf(mx, f[i]);
    red[tid] = mx; __syncthreads();
    for (int o = 128; o > 0; o >>= 1) {
        if (tid < o) red[tid] = fmaxf(red[tid], red[tid + o]);
        __syncthreads();
    }
    mx = red[0];
    __syncthreads();

    float sum = 0.f;
#pragma unroll
    for (int i = 0; i < 16; i++) {
        f[i] = __expf((f[i] - mx) * scale);
        sum += f[i];
    }
    red[tid] = sum; __syncthreads();
    for (int o = 128; o > 0; o >>= 1) {
        if (tid < o) red[tid] += red[tid + o];
        __syncthreads();
    }
    const float inv = 1.f / red[0];
#pragma unroll
    for (int ii = 0; ii < 2; ii++) {
        uint32_t* w = (uint32_t*)&u[ii];
#pragma unroll
        for (int j = 0; j < 4; j++) {
            __half2 h = __floats2half2_rn(f[ii * 8 + j * 2] * inv,
                                          f[ii * 8 + j * 2 + 1] * inv);
            w[j] = *(const uint32_t*)&h;
        }
    }
    p[tid]       = u[0];
    p[tid + 256] = u[1];
}

__global__ void zero_acc_kernel()
{
    if (threadIdx.x < 32) g_acc[threadIdx.x] = 0.0;
}

// normalize y in place (fp32) + write fp16 copy
__global__ void apply1_kernel(float* __restrict__ y, __half* __restrict__ yh)
{
    const int b = blockIdx.y;
    const double sum = g_acc[2 * b], sq = g_acc[2 * b + 1];
    const double NE = (double)SS * DD;
    const double mean = sum / NE;
    double var = sq - NE * mean * mean;
    if (var < 0.0) var = 0.0;
    const float inv = (float)(1.0 / (sqrt(var) + 1e-7));
    const float fm = (float)mean;

    float4* y4 = ((float4*)y) + (long long)b * (SS * DD / 4);
    __half2* yh2 = ((__half2*)yh) + (long long)b * (SS * DD / 2);
    const long long i = (long long)blockIdx.x * 256 + threadIdx.x;  // grid.x = 2048
    float4 vv = y4[i];
    vv.x = (vv.x - fm) * inv; vv.y = (vv.y - fm) * inv;
    vv.z = (vv.z - fm) * inv; vv.w = (vv.w - fm) * inv;
    y4[i] = vv;
    yh2[i * 2]     = __floats2half2_rn(vv.x, vv.y);
    yh2[i * 2 + 1] = __floats2half2_rn(vv.z, vv.w);
}

// out[b,d,s] = (y2[b,s,d] - mean) * inv
__global__ void apply2t_kernel(const float* __restrict__ y2, float* __restrict__ out)
{
    const int b = blockIdx.z;
    const double sum = g_acc[16 + 2 * b], sq = g_acc[16 + 2 * b + 1];
    const double NE = (double)SS * DD;
    const double mean = sum / NE;
    double var = sq - NE * mean * mean;
    if (var < 0.0) var = 0.0;
    const float inv = (float)(1.0 / (sqrt(var) + 1e-7));
    const float fm = (float)mean;

    const int s0 = blockIdx.x * 32;
    const int d0 = blockIdx.y * 32;
    __shared__ float ys[32][33];
    const int tx = threadIdx.x, ty = threadIdx.y;

#pragma unroll
    for (int i = 0; i < 32; i += 8)
        ys[ty + i][tx] = y2[((long long)b * SS + s0 + ty + i) * DD + d0 + tx];
    __syncthreads();
#pragma unroll
    for (int i = 0; i < 32; i += 8)
        out[((long long)b * DD + d0 + ty + i) * SS + s0 + tx] =
            (ys[tx][ty + i] - fm) * inv;
}

// ---------------- host-side orchestration ----------------
template <typename T>
static T* sym(const void* symbol)
{
    void* p = nullptr;
    cudaGetSymbolAddress(&p, symbol);
    return (T*)p;
}

extern "C" void kernel_launch(void* const* d_in, const int* in_sizes, int n_in,
                              void* d_out, int out_size)
{
    const float* x  = (const float*)d_in[0];
    const float* Wq = (const float*)d_in[1];
    const float* Wk = (const float*)d_in[2];
    const float* Wv = (const float*)d_in[3];
    const float* Wo = (const float*)d_in[4];
    const float* W1 = (const float*)d_in[5];
    const float* b1 = (const float*)d_in[6];
    const float* W2 = (const float*)d_in[7];
    const float* b2 = (const float*)d_in[8];
    float* out = (float*)d_out;

    float*  py    = sym<float>((const void*)g_y);
    float*  ph2   = sym<float>((const void*)g_h2);
    double* pacc  = sym<double>((const void*)g_acc);
    __half* pxh   = sym<__half>((const void*)g_xh);
    __half* pqh   = sym<__half>((const void*)g_qh);
    __half* pkh   = sym<__half>((const void*)g_kh);
    __half* pvt   = sym<__half>((const void*)g_vt);
    __half* psh   = sym<__half>((const void*)g_sh);
    __half* pyh   = sym<__half>((const void*)g_yh);
    __half* ph1h  = sym<__half>((const void*)g_h1h);
    __half* pwqT  = sym<__half>((const void*)g_wqT);
    __half* pwkT  = sym<__half>((const void*)g_wkT);
    __half* pwvh  = sym<__half>((const void*)g_wvh);
    __half* pwoT  = sym<__half>((const void*)g_woT);
    __half* pwvoT = sym<__half>((const void*)g_wvoT);
    __half* pw1T  = sym<__half>((const void*)g_w1T);
    __half* pw2T  = sym<__half>((const void*)g_w2T);

    const long long sSD = (long long)SS * DD;
    const long long sSS = (long long)SS * SS;
    const long long sSF = (long long)SS * FF;
    const long long sDS = (long long)DD * SS;

    cudaFuncSetAttribute(gemm_h<0, 1, 128>, cudaFuncAttributeMaxDynamicSharedMemorySize, SMEMB128);
    cudaFuncSetAttribute(gemm_h<0, 2, 128>, cudaFuncAttributeMaxDynamicSharedMemorySize, SMEMB128);
    cudaFuncSetAttribute(gemm_h<3, 0, 128>, cudaFuncAttributeMaxDynamicSharedMemorySize, SMEMB128);
    cudaFuncSetAttribute(gemm_h<4, 0, 128>, cudaFuncAttributeMaxDynamicSharedMemorySize, SMEMB128);
    cudaFuncSetAttribute(gemm_h<0, 1, 256>, cudaFuncAttributeMaxDynamicSharedMemorySize, SMEMB256);
    cudaFuncSetAttribute(gemm_h<2, 1, 256>, cudaFuncAttributeMaxDynamicSharedMemorySize, SMEMB256);

    zero_acc_kernel<<<1, 32>>>();

    // pre-pass: fp16 operands
    dim3 tblk(32, 8);
    transpose_h<<<dim3(SS / 32, DD / 32, BB), tblk>>>(x,  pxh,  DD, SS); // x[b]:[D,S]->[S,D]
    transpose_h<<<dim3(DD / 32, DD / 32, 1), tblk>>>(Wq, pwqT, DD, DD);
    transpose_h<<<dim3(DD / 32, DD / 32, 1), tblk>>>(Wk, pwkT, DD, DD);
    transpose_h<<<dim3(DD / 32, DD / 32, 1), tblk>>>(Wo, pwoT, DD, DD);
    convert_h<<<DD * DD / 1024, 256>>>(Wv, pwvh);                        // Wv fp16 (no transpose)
    transpose_h<<<dim3(FF / 32, DD / 32, 1), tblk>>>(W1, pw1T, DD, FF); // [D,F]->[F,D]
    transpose_h<<<dim3(DD / 32, FF / 32, 1), tblk>>>(W2, pw2T, FF, DD); // [F,D]->[D,F]

    dim3 gW(DD / 128, DD / 128, 1);          // (4,4,1) weight-product GEMM
    dim3 gNarrow(DD / 128, SS / 128, BB);    // (4,32,8)
    dim3 gScoreW(SS / 256, SS / 128, BB);    // (16,32,8) wide
    dim3 gFFNW(FF / 256, SS / 128, BB);      // (8,32,8) wide

    // W_voT[m,n] = sum_k WoT[m,k] * Wv[n,k]  ( = (Wv@Wo)^T )
    gemm_h<0, 1, 128><<<gW, 128, SMEMB128>>>(pwoT, pwvh, nullptr, pwvoT,
        DD, DD, DD, DD, 0, 0, 0, nullptr, 0, nullptr);

    // q,k = xh @ WT  (fp16 out)
    gemm_h<0, 1, 128><<<gNarrow, 128, SMEMB128>>>(pxh, pwqT, nullptr, pqh,
        DD, DD, DD, DD, sSD, 0, sSD, nullptr, 0, nullptr);
    gemm_h<0, 1, 128><<<gNarrow, 128, SMEMB128>>>(pxh, pwkT, nullptr, pkh,
        DD, DD, DD, DD, sSD, 0, sSD, nullptr, 0, nullptr);
    // v' = xh @ (WvWo)^T (fp16 out, transposed to [D,S])
    gemm_h<0, 2, 128><<<gNarrow, 128, SMEMB128>>>(pxh, pwvoT, nullptr, pvt,
        DD, DD, DD, SS, sSD, 0, sDS, nullptr, 0, nullptr);

    // scores = q @ k^T (fp16 out, wide 128x256 tile)
    gemm_h<0, 1, 256><<<gScoreW, 256, SMEMB256>>>(pqh, pkh, nullptr, psh,
        DD, DD, DD, SS, sSD, sSD, sSS, nullptr, 0, nullptr);

    softmax_h<<<BB * SS, 256>>>(psh, 0.04419417382415922f /* 1/sqrt(512) */);

    // y = attn @ v' + x^T  (fused residual + stats stage 0, fp32 out)
    gemm_h<3, 0, 128><<<gNarrow, 128, SMEMB128>>>(psh, pvt, nullptr, py,
        SS, SS, SS, DD, sSS, sDS, sSD, x, sDS, pacc);

    apply1_kernel<<<dim3(2048, BB), 256>>>(py, pyh);

    // FFN (W1 wide 128x256 tile)
    gemm_h<2, 1, 256><<<gFFNW, 256, SMEMB256>>>(pyh, pw1T, b1, ph1h,
        DD, DD, DD, FF, sSD, 0, sSF, nullptr, 0, nullptr);
    // h2 = h1 @ W2 + b2 + y  (fused residual + stats stage 1, fp32 out)
    gemm_h<4, 0, 128><<<gNarrow, 128, SMEMB128>>>(ph1h, pw2T, b2, ph2,
        FF, FF, FF, DD, sSF, 0, sSD, py, sSD, pacc + 16);

    apply2t_kernel<<<dim3(SS / 32, DD / 32, BB), tblk>>>(ph2, out);

    (void)in_sizes; (void)n_in; (void)out_size;
}

// round 12
// speedup vs baseline: 1.0310x; 1.0310x over previous
#include <cuda_runtime.h>
#include <cuda_fp16.h>
#include <math.h>
#include <stdint.h>

// Problem constants
#define BB 8
#define DD 512
#define SS 4096
#define FF 2048

// ---------------- static scratch (no allocations allowed) ----------------
// fp32
__device__ float g_y [(size_t)BB * SS * DD];      // raw residual-1 (unnormalized)
__device__ float g_h2[(size_t)BB * SS * DD];
__device__ double g_acc[32];
// fp16 operands (row-major [x][k] for every GEMM)
__device__ __half g_xh  [(size_t)BB * SS * DD];   // x^T  [B,S,D]
__device__ __half g_qkh [(size_t)BB * SS * 2 * DD]; // [B,S,2D]: q | k
__device__ __half g_vt  [(size_t)BB * DD * SS];   // v'^T [B,D,S]  (v' = x^T Wv Wo)
__device__ __half g_sh  [(size_t)BB * SS * SS];   // scores/attn fp16
__device__ __half g_yh  [(size_t)BB * SS * DD];   // normalized post, fp16 copy
__device__ __half g_h1h [(size_t)BB * SS * FF];
__device__ __half g_wqkT[2 * DD * DD];            // [2D, D]: WqT rows 0..511, WkT rows 512..1023
__device__ __half g_wvh [DD * DD];                // Wv fp16, NOT transposed
__device__ __half g_woT [DD * DD];
__device__ __half g_wvoT[DD * DD];                // (Wv@Wo)^T fp16
__device__ __half g_w1T [(size_t)DD * FF];        // [F,D]
__device__ __half g_w2T [(size_t)DD * FF];        // [D,F]

// ---------------- helpers ----------------
__device__ __forceinline__ uint32_t smem_u32(const void* p)
{
    uint32_t a;
    asm("{ .reg .u64 t; cvta.to.shared.u64 t, %1; cvt.u32.u64 %0, t; }" : "=r"(a) : "l"(p));
    return a;
}

#define CP16(d, s) asm volatile("cp.async.ca.shared.global [%0], [%1], 16;" :: "r"(d), "l"(s))
#define CPC()  asm volatile("cp.async.commit_group;" ::: "memory")
#define CPW0() asm volatile("cp.async.wait_group 0;" ::: "memory")
#define CPW1() asm volatile("cp.async.wait_group 1;" ::: "memory")

#define LDMX4(r, addr) \
    asm volatile("ldmatrix.sync.aligned.m8n8.x4.shared.b16 {%0,%1,%2,%3}, [%4];" \
        : "=r"((r)[0]), "=r"((r)[1]), "=r"((r)[2]), "=r"((r)[3]) : "r"(addr))

__device__ __forceinline__ void mma16816(float c[4], const uint32_t a[4],
                                         uint32_t b0, uint32_t b1)
{
    asm volatile(
        "mma.sync.aligned.m16n8k16.row.col.f32.f16.f16.f32 "
        "{%0,%1,%2,%3}, {%4,%5,%6,%7}, {%8,%9}, {%0,%1,%2,%3};\n"
        : "+f"(c[0]), "+f"(c[1]), "+f"(c[2]), "+f"(c[3])
        : "r"(a[0]), "r"(a[1]), "r"(a[2]), "r"(a[3]),
          "r"(b0), "r"(b1));
}

// ---------------- fp16 tensor-core GEMM, 2-stage cp.async + ldmatrix ----------------
// 128 threads (4 warps), warp tile 64x64, CTA tile 128x128, TK=64.
// C[M,N] = A[M,K] * B[N,K]^T, A/B fp16 row-major.
// EPI: 0 none, 1 +bias, 2 relu(+bias),
//      3 +residual from res[N,M]-layout (x^T, ld=SS) + stats -> fp32 out
//      4 +bias +normalize(res[M,N], stats0) residual + stats -> fp32 out
// OUT: 0 fp32 [M,N]; 1 fp16 [M,N]; 2 fp16 transposed [N,M]
#define SKB 144                     // smem row stride in bytes
#define TILE_B (128 * SKB)          // 18432 bytes
#define SMEMB (4 * TILE_B)          // 73728 bytes (2 stages x (A+B)) -> 2 CTAs/SM

template <int EPI, int OUT>
__global__ __launch_bounds__(128)
void gemm_h(const __half* __restrict__ A, const __half* __restrict__ B,
            const float* __restrict__ bias, void* __restrict__ Cv,
            int K, int lda, int ldb, int ldc,
            long long sA, long long sB, long long sC,
            const float* __restrict__ res, long long sR,
            double* __restrict__ stats, const double* __restrict__ stats0)
{
    extern __shared__ char smem[];
    const uint32_t base = smem_u32(smem);

    const int bz = blockIdx.z;
    const __half* Ab = A + (long long)bz * sA;
    const __half* Bb = B + (long long)bz * sB;

    const int m0 = blockIdx.y * 128;
    const int n0 = blockIdx.x * 128;
    const int tid  = threadIdx.x;
    const int lane = tid & 31;
    const int warp = tid >> 5;
    const int wm = (warp >> 1) * 64;   // 0 / 64
    const int wn = (warp & 1) * 64;    // 0 / 64
    const int qr = lane >> 2;   // 0..7
    const int qc = lane & 3;    // 0..3

    float acc[4][8][4];
#pragma unroll
    for (int i = 0; i < 4; i++)
#pragma unroll
        for (int j = 0; j < 8; j++)
#pragma unroll
            for (int q = 0; q < 4; q++) acc[i][j][q] = 0.f;

    const int NKB = K >> 6;

    // staging: each operand tile = 128 rows x 128B; 1024 16B chunks, 8/thread
    const int sx = tid >> 3;       // row 0..15 (+16 per iter)
    const int sc = tid & 7;        // 16B chunk in row
    const uint32_t sdst = (uint32_t)(sx * SKB + sc * 16);

#define STAGE(buf, k0)                                                          \
    do {                                                                        \
        const uint32_t aD = base + (buf) * TILE_B + sdst;                       \
        const uint32_t bD = base + (2 + (buf)) * TILE_B + sdst;                 \
        const __half* aSrc = Ab + (long long)(m0 + sx) * lda + (k0) + sc * 8;   \
        const __half* bSrc = Bb + (long long)(n0 + sx) * ldb + (k0) + sc * 8;   \
        _Pragma("unroll")                                                       \
        for (int it = 0; it < 8; it++) {                                        \
            CP16(aD + it * (16 * SKB), aSrc + (long long)(it * 16) * lda);      \
            CP16(bD + it * (16 * SKB), bSrc + (long long)(it * 16) * ldb);      \
        }                                                                       \
    } while (0)

    STAGE(0, 0);
    CPC();

    // per-lane ldmatrix offsets: lanes 0-15 -> rows (x&15) @ +0B, 16-31 -> @ +16B
    const uint32_t aOff = (uint32_t)((wm + (lane & 15)) * SKB + (lane >> 4) * 16);
    const uint32_t bOff = (uint32_t)((wn + (lane & 15)) * SKB + (lane >> 4) * 16);

    for (int kb = 0; kb < NKB; kb++) {
        const int cur = kb & 1;
        if (kb + 1 < NKB) {
            STAGE(cur ^ 1, (kb + 1) << 6);
            CPC();
            CPW1();
        } else {
            CPW0();
        }
        __syncthreads();

        const uint32_t aT = base + cur * TILE_B + aOff;
        const uint32_t bT = base + (2 + cur) * TILE_B + bOff;
#pragma unroll
        for (int ks = 0; ks < 4; ks++) {
            uint32_t af[4][4], bq[4][4];
#pragma unroll
            for (int mi = 0; mi < 4; mi++)
                LDMX4(af[mi], aT + mi * (16 * SKB) + ks * 32);
#pragma unroll
            for (int ni = 0; ni < 4; ni++)
                LDMX4(bq[ni], bT + ni * (16 * SKB) + ks * 32);
#pragma unroll
            for (int mi = 0; mi < 4; mi++)
#pragma unroll
                for (int ni = 0; ni < 4; ni++) {
                    mma16816(acc[mi][2 * ni],     af[mi], bq[ni][0], bq[ni][2]);
                    mma16816(acc[mi][2 * ni + 1], af[mi], bq[ni][1], bq[ni][3]);
                }
        }
        __syncthreads();
    }
#undef STAGE

    // ---- epilogue ----
    const float* resb = (EPI >= 3) ? (res + (long long)bz * sR) : nullptr;
    float ls = 0.f, lq = 0.f;
    float nfm = 0.f, ninv = 1.f;
    if (EPI == 4) {
        // stage-0 normalization constants (same formula as apply1h)
        const double sum = stats0[2 * bz], sq = stats0[2 * bz + 1];
        const double NE = (double)SS * DD;
        const double mean = sum / NE;
        double var = sq - NE * mean * mean;
        if (var < 0.0) var = 0.0;
        ninv = (float)(1.0 / (sqrt(var) + 1e-7));
        nfm  = (float)mean;
    }

#pragma unroll
    for (int mi = 0; mi < 4; mi++) {
        const int m = m0 + wm + mi * 16 + qr;
#pragma unroll
        for (int ni = 0; ni < 8; ni++) {
            const int nc = n0 + wn + ni * 8 + 2 * qc;
            float c0 = acc[mi][ni][0], c1 = acc[mi][ni][1];
            float c2 = acc[mi][ni][2], c3 = acc[mi][ni][3];
            if (EPI == 1 || EPI == 2 || EPI == 4) {
                const float bx = bias[nc], by = bias[nc + 1];
                c0 += bx; c1 += by; c2 += bx; c3 += by;
            }
            if (EPI == 2) {
                c0 = fmaxf(c0, 0.f); c1 = fmaxf(c1, 0.f);
                c2 = fmaxf(c2, 0.f); c3 = fmaxf(c3, 0.f);
            }
            if (EPI == 3) {
                // residual stored [N, M] (x^T layout, ld = SS)
                c0 += resb[(long long)nc * SS + m];
                c1 += resb[(long long)(nc + 1) * SS + m];
                c2 += resb[(long long)nc * SS + m + 8];
                c3 += resb[(long long)(nc + 1) * SS + m + 8];
            }
            if (EPI == 4) {
                // residual stored [M, N] raw (ld = DD), normalized on the fly
                const float2 r0 = *(const float2*)(resb + (long long)m * DD + nc);
                const float2 r1 = *(const float2*)(resb + (long long)(m + 8) * DD + nc);
                c0 += (r0.x - nfm) * ninv; c1 += (r0.y - nfm) * ninv;
                c2 += (r1.x - nfm) * ninv; c3 += (r1.y - nfm) * ninv;
            }
            if (EPI >= 3) {
                ls += c0 + c1 + c2 + c3;
                lq += c0 * c0 + c1 * c1 + c2 * c2 + c3 * c3;
            }
            if (OUT == 0) {
                float* C = (float*)Cv + (long long)bz * sC;
                float2 lo; lo.x = c0; lo.y = c1;
                float2 hi; hi.x = c2; hi.y = c3;
                *(float2*)(C + (long long)m * ldc + nc) = lo;
                *(float2*)(C + (long long)(m + 8) * ldc + nc) = hi;
            } else if (OUT == 1) {
                __half* C = (__half*)Cv + (long long)bz * sC;
                *(__half2*)(C + (long long)m * ldc + nc) = __floats2half2_rn(c0, c1);
                *(__half2*)(C + (long long)(m + 8) * ldc + nc) = __floats2half2_rn(c2, c3);
            } else {
                __half* C = (__half*)Cv + (long long)bz * sC;
                C[(long long)nc * ldc + m]           = __float2half_rn(c0);
                C[(long long)(nc + 1) * ldc + m]     = __float2half_rn(c1);
                C[(long long)nc * ldc + m + 8]       = __float2half_rn(c2);
                C[(long long)(nc + 1) * ldc + m + 8] = __float2half_rn(c3);
            }
        }
    }

    if (EPI >= 3) {
        // block-reduce ls/lq into per-batch stats (reuse GEMM smem; mainloop done)
        float* sa = (float*)smem;
        float* sb = sa + 128;
        sa[tid] = ls; sb[tid] = lq;
        __syncthreads();
        for (int o = 64; o > 0; o >>= 1) {
            if (tid < o) { sa[tid] += sa[tid + o]; sb[tid] += sb[tid + o]; }
            __syncthreads();
        }
        if (tid == 0) {
            atomicAdd(stats + 2 * bz + 0, (double)sa[0]);
            atomicAdd(stats + 2 * bz + 1, (double)sb[0]);
        }
    }
}

// ---------------- transpose + fp32->fp16 convert: src[R,C] -> dst[C,R] ----------------
__global__ void transpose_h(const float* __restrict__ src, __half* __restrict__ dst,
                            int R, int C)
{
    const int b = blockIdx.z;
    src += (long long)b * R * C;
    dst += (long long)b * R * C;
    const int r0 = blockIdx.y * 32;
    const int c0 = blockIdx.x * 32;
    __shared__ float t[32][33];
    const int tx = threadIdx.x, ty = threadIdx.y;   // 32 x 8
#pragma unroll
    for (int i = 0; i < 32; i += 8)
        t[ty + i][tx] = src[(long long)(r0 + ty + i) * C + c0 + tx];
    __syncthreads();
#pragma unroll
    for (int i = 0; i < 32; i += 8)
        dst[(long long)(c0 + ty + i) * R + r0 + tx] = __float2half_rn(t[tx][ty + i]);
}

// ---------------- straight fp32->fp16 convert ----------------
__global__ void convert_h(const float* __restrict__ src, __half* __restrict__ dst)
{
    const long long i = (long long)blockIdx.x * 256 + threadIdx.x;
    const float4 v = ((const float4*)src)[i];
    __half2* d = (__half2*)dst + i * 2;
    d[0] = __floats2half2_rn(v.x, v.y);
    d[1] = __floats2half2_rn(v.z, v.w);
}

// ---------------- softmax on fp16 scores (in place, scaled) ----------------
__global__ void softmax_h(__half* __restrict__ sh, float scale)
{
    const long long row = blockIdx.x;
    uint4* p = (uint4*)(sh + row * SS);       // 512 uint4 per row (8 halves each)
    const int tid = threadIdx.x;              // 256 threads, 2 uint4 each
    __shared__ float red[256];

    uint4 u[2];
    float f[16];
    u[0] = p[tid];
    u[1] = p[tid + 256];
#pragma unroll
    for (int ii = 0; ii < 2; ii++) {
        const uint32_t* w = (const uint32_t*)&u[ii];
#pragma unroll
        for (int j = 0; j < 4; j++) {
            float2 d = __half22float2(*(const __half2*)&w[j]);
            f[ii * 8 + j * 2]     = d.x;
            f[ii * 8 + j * 2 + 1] = d.y;
        }
    }
    float mx = -INFINITY;
#pragma unroll
    for (int i = 0; i < 16; i++) mx = fmaxf(mx, f[i]);
    red[tid] = mx; __syncthreads();
    for (int o = 128; o > 0; o >>= 1) {
        if (tid < o) red[tid] = fmaxf(red[tid], red[tid + o]);
        __syncthreads();
    }
    mx = red[0];
    __syncthreads();

    float sum = 0.f;
#pragma unroll
    for (int i = 0; i < 16; i++) {
        f[i] = __expf((f[i] - mx) * scale);
        sum += f[i];
    }
    red[tid] = sum; __syncthreads();
    for (int o = 128; o > 0; o >>= 1) {
        if (tid < o) red[tid] += red[tid + o];
        __syncthreads();
    }
    const float inv = 1.f / red[0];
#pragma unroll
    for (int ii = 0; ii < 2; ii++) {
        uint32_t* w = (uint32_t*)&u[ii];
#pragma unroll
        for (int j = 0; j < 4; j++) {
            __half2 h = __floats2half2_rn(f[ii * 8 + j * 2] * inv,
                                          f[ii * 8 + j * 2 + 1] * inv);
            w[j] = *(const uint32_t*)&h;
        }
    }
    p[tid]       = u[0];
    p[tid + 256] = u[1];
}

__global__ void zero_acc_kernel()
{
    if (threadIdx.x < 32) g_acc[threadIdx.x] = 0.0;
}

// read raw y, write ONLY normalized fp16 copy (fp32 y stays raw for EPI=4)
__global__ void apply1h_kernel(const float* __restrict__ y, __half* __restrict__ yh)
{
    const int b = blockIdx.y;
    const double sum = g_acc[2 * b], sq = g_acc[2 * b + 1];
    const double NE = (double)SS * DD;
    const double mean = sum / NE;
    double var = sq - NE * mean * mean;
    if (var < 0.0) var = 0.0;
    const float inv = (float)(1.0 / (sqrt(var) + 1e-7));
    const float fm = (float)mean;

    const float4* y4 = ((const float4*)y) + (long long)b * (SS * DD / 4);
    __half2* yh2 = ((__half2*)yh) + (long long)b * (SS * DD / 2);
    const long long i = (long long)blockIdx.x * 256 + threadIdx.x;  // grid.x = 2048
    float4 vv = y4[i];
    vv.x = (vv.x - fm) * inv; vv.y = (vv.y - fm) * inv;
    vv.z = (vv.z - fm) * inv; vv.w = (vv.w - fm) * inv;
    yh2[i * 2]     = __floats2half2_rn(vv.x, vv.y);
    yh2[i * 2 + 1] = __floats2half2_rn(vv.z, vv.w);
}

// out[b,d,s] = (y2[b,s,d] - mean) * inv
__global__ void apply2t_kernel(const float* __restrict__ y2, float* __restrict__ out)
{
    const int b = blockIdx.z;
    const double sum = g_acc[16 + 2 * b], sq = g_acc[16 + 2 * b + 1];
    const double NE = (double)SS * DD;
    const double mean = sum / NE;
    double var = sq - NE * mean * mean;
    if (var < 0.0) var = 0.0;
    const float inv = (float)(1.0 / (sqrt(var) + 1e-7));
    const float fm = (float)mean;

    const int s0 = blockIdx.x * 32;
    const int d0 = blockIdx.y * 32;
    __shared__ float ys[32][33];
    const int tx = threadIdx.x, ty = threadIdx.y;

#pragma unroll
    for (int i = 0; i < 32; i += 8)
        ys[ty + i][tx] = y2[((long long)b * SS + s0 + ty + i) * DD + d0 + tx];
    __syncthreads();
#pragma unroll
    for (int i = 0; i < 32; i += 8)
        out[((long long)b * DD + d0 + ty + i) * SS + s0 + tx] =
            (ys[tx][ty + i] - fm) * inv;
}

// ---------------- host-side orchestration ----------------
template <typename T>
static T* sym(const void* symbol)
{
    void* p = nullptr;
    cudaGetSymbolAddress(&p, symbol);
    return (T*)p;
}

extern "C" void kernel_launch(void* const* d_in, const int* in_sizes, int n_in,
                              void* d_out, int out_size)
{
    const float* x  = (const float*)d_in[0];
    const float* Wq = (const float*)d_in[1];
    const float* Wk = (const float*)d_in[2];
    const float* Wv = (const float*)d_in[3];
    const float* Wo = (const float*)d_in[4];
    const float* W1 = (const float*)d_in[5];
    const float* b1 = (const float*)d_in[6];
    const float* W2 = (const float*)d_in[7];
    const float* b2 = (const float*)d_in[8];
    float* out = (float*)d_out;

    float*  py    = sym<float>((const void*)g_y);
    float*  ph2   = sym<float>((const void*)g_h2);
    double* pacc  = sym<double>((const void*)g_acc);
    __half* pxh   = sym<__half>((const void*)g_xh);
    __half* pqkh  = sym<__half>((const void*)g_qkh);
    __half* pvt   = sym<__half>((const void*)g_vt);
    __half* psh   = sym<__half>((const void*)g_sh);
    __half* pyh   = sym<__half>((const void*)g_yh);
    __half* ph1h  = sym<__half>((const void*)g_h1h);
    __half* pwqkT = sym<__half>((const void*)g_wqkT);
    __half* pwvh  = sym<__half>((const void*)g_wvh);
    __half* pwoT  = sym<__half>((const void*)g_woT);
    __half* pwvoT = sym<__half>((const void*)g_wvoT);
    __half* pw1T  = sym<__half>((const void*)g_w1T);
    __half* pw2T  = sym<__half>((const void*)g_w2T);

    const long long sSD  = (long long)SS * DD;
    const long long sS2D = (long long)SS * 2 * DD;
    const long long sSS  = (long long)SS * SS;
    const long long sSF  = (long long)SS * FF;
    const long long sDS  = (long long)DD * SS;

    cudaFuncSetAttribute(gemm_h<0, 1>, cudaFuncAttributeMaxDynamicSharedMemorySize, SMEMB);
    cudaFuncSetAttribute(gemm_h<0, 2>, cudaFuncAttributeMaxDynamicSharedMemorySize, SMEMB);
    cudaFuncSetAttribute(gemm_h<2, 1>, cudaFuncAttributeMaxDynamicSharedMemorySize, SMEMB);
    cudaFuncSetAttribute(gemm_h<3, 0>, cudaFuncAttributeMaxDynamicSharedMemorySize, SMEMB);
    cudaFuncSetAttribute(gemm_h<4, 0>, cudaFuncAttributeMaxDynamicSharedMemorySize, SMEMB);

    zero_acc_kernel<<<1, 32>>>();

    // pre-pass: fp16 operands
    dim3 tblk(32, 8);
    transpose_h<<<dim3(SS / 32, DD / 32, BB), tblk>>>(x,  pxh,  DD, SS); // x[b]:[D,S]->[S,D]
    transpose_h<<<dim3(DD / 32, DD / 32, 1), tblk>>>(Wq, pwqkT,           DD, DD);
    transpose_h<<<dim3(DD / 32, DD / 32, 1), tblk>>>(Wk, pwqkT + DD * DD, DD, DD);
    transpose_h<<<dim3(DD / 32, DD / 32, 1), tblk>>>(Wo, pwoT, DD, DD);
    convert_h<<<DD * DD / 1024, 256>>>(Wv, pwvh);                        // Wv fp16 (no transpose)
    transpose_h<<<dim3(FF / 32, DD / 32, 1), tblk>>>(W1, pw1T, DD, FF); // [D,F]->[F,D]
    transpose_h<<<dim3(DD / 32, FF / 32, 1), tblk>>>(W2, pw2T, FF, DD); // [F,D]->[D,F]

    dim3 blk(128);
    dim3 gW(DD / 128, DD / 128, 1);          // (4,4,1) weight-product GEMM
    dim3 gQK(2 * DD / 128, SS / 128, BB);    // (8,32,8) merged q|k projection
    dim3 gNarrow(DD / 128, SS / 128, BB);    // (4,32,8)
    dim3 gScore(SS / 128, SS / 128, BB);     // (32,32,8)
    dim3 gFFN(FF / 128, SS / 128, BB);       // (16,32,8)

    // W_voT[m,n] = sum_k WoT[m,k] * Wv[n,k]  ( = (Wv@Wo)^T )
    gemm_h<0, 1><<<gW, blk, SMEMB>>>(pwoT, pwvh, nullptr, pwvoT,
        DD, DD, DD, DD, 0, 0, 0, nullptr, 0, nullptr, nullptr);

    // qk = xh @ [WqT|WkT]^T  (fp16 out, N=1024 merged)
    gemm_h<0, 1><<<gQK, blk, SMEMB>>>(pxh, pwqkT, nullptr, pqkh,
        DD, DD, DD, 2 * DD, sSD, 0, sS2D, nullptr, 0, nullptr, nullptr);
    // v' = xh @ (WvWo)^T (fp16 out, transposed to [D,S])
    gemm_h<0, 2><<<gNarrow, blk, SMEMB>>>(pxh, pwvoT, nullptr, pvt,
        DD, DD, DD, SS, sSD, 0, sDS, nullptr, 0, nullptr, nullptr);

    // scores = q @ k^T (A = qk cols 0..511, B = qk cols 512..1023; fp16 out)
    gemm_h<0, 1><<<gScore, blk, SMEMB>>>(pqkh, pqkh + DD, nullptr, psh,
        DD, 2 * DD, 2 * DD, SS, sS2D, sS2D, sSS, nullptr, 0, nullptr, nullptr);

    softmax_h<<<BB * SS, 256>>>(psh, 0.04419417382415922f /* 1/sqrt(512) */);

    // y = attn @ v' + x^T  (fused residual + stats stage 0, raw fp32 out)
    gemm_h<3, 0><<<gNarrow, blk, SMEMB>>>(psh, pvt, nullptr, py,
        SS, SS, SS, DD, sSS, sDS, sSD, x, sDS, pacc, nullptr);

    apply1h_kernel<<<dim3(2048, BB), 256>>>(py, pyh);

    // FFN
    gemm_h<2, 1><<<gFFN, blk, SMEMB>>>(pyh, pw1T, b1, ph1h,
        DD, DD, DD, FF, sSD, 0, sSF, nullptr, 0, nullptr, nullptr);
    // h2 = h1 @ W2 + b2 + normalize(y)  (fused residual + stats stage 1, fp32 out)
    gemm_h<4, 0><<<gNarrow, blk, SMEMB>>>(ph1h, pw2T, b2, ph2,
        FF, FF, FF, DD, sSF, 0, sSD, py, sSD, pacc + 16, pacc);

    apply2t_kernel<<<dim3(SS / 32, DD / 32, BB), tblk>>>(ph2, out);

    (void)in_sizes; (void)n_in; (void)out_size;
}

// round 13
// speedup vs baseline: 1.0729x; 1.0406x over previous
#include <cuda_runtime.h>
#include <cuda_fp16.h>
#include <math.h>
#include <stdint.h>

// Problem constants
#define BB 8
#define DD 512
#define SS 4096
#define FF 2048

// ---------------- static scratch (no allocations allowed) ----------------
// fp32
__device__ float g_y [(size_t)BB * SS * DD];      // raw residual-1 (unnormalized)
__device__ float g_h2[(size_t)BB * SS * DD];
__device__ float g_rowsum[(size_t)BB * SS];       // attention row sums (unnormalized exp)
__device__ double g_acc[32];
// fp16 operands (row-major [x][k] for every GEMM)
__device__ __half g_xh  [(size_t)BB * SS * DD];   // x^T  [B,S,D]
__device__ __half g_qkh [(size_t)BB * SS * 2 * DD]; // [B,S,2D]: q | k
__device__ __half g_vt  [(size_t)BB * DD * SS];   // v'^T [B,D,S]  (v' = x^T Wv Wo)
__device__ __half g_sh  [(size_t)BB * SS * SS];   // unnormalized exp scores, fp16
__device__ __half g_yh  [(size_t)BB * SS * DD];   // normalized post, fp16 copy
__device__ __half g_h1h [(size_t)BB * SS * FF];
__device__ __half g_wqkT[2 * DD * DD];            // [2D, D]: WqT rows 0..511, WkT rows 512..1023
__device__ __half g_wvh [DD * DD];                // Wv fp16, NOT transposed
__device__ __half g_woT [DD * DD];
__device__ __half g_wvoT[DD * DD];                // (Wv@Wo)^T fp16
__device__ __half g_w1T [(size_t)DD * FF];        // [F,D]
__device__ __half g_w2T [(size_t)DD * FF];        // [D,F]

// ---------------- helpers ----------------
__device__ __forceinline__ uint32_t smem_u32(const void* p)
{
    uint32_t a;
    asm("{ .reg .u64 t; cvta.to.shared.u64 t, %1; cvt.u32.u64 %0, t; }" : "=r"(a) : "l"(p));
    return a;
}

#define CP16(d, s) asm volatile("cp.async.ca.shared.global [%0], [%1], 16;" :: "r"(d), "l"(s))
#define CPC()  asm volatile("cp.async.commit_group;" ::: "memory")
#define CPW0() asm volatile("cp.async.wait_group 0;" ::: "memory")
#define CPW1() asm volatile("cp.async.wait_group 1;" ::: "memory")

#define LDMX4(r, addr) \
    asm volatile("ldmatrix.sync.aligned.m8n8.x4.shared.b16 {%0,%1,%2,%3}, [%4];" \
        : "=r"((r)[0]), "=r"((r)[1]), "=r"((r)[2]), "=r"((r)[3]) : "r"(addr))

__device__ __forceinline__ void mma16816(float c[4], const uint32_t a[4],
                                         uint32_t b0, uint32_t b1)
{
    asm volatile(
        "mma.sync.aligned.m16n8k16.row.col.f32.f16.f16.f32 "
        "{%0,%1,%2,%3}, {%4,%5,%6,%7}, {%8,%9}, {%0,%1,%2,%3};\n"
        : "+f"(c[0]), "+f"(c[1]), "+f"(c[2]), "+f"(c[3])
        : "r"(a[0]), "r"(a[1]), "r"(a[2]), "r"(a[3]),
          "r"(b0), "r"(b1));
}

// ---------------- fp16 tensor-core GEMM, 2-stage cp.async + ldmatrix ----------------
// 128 threads (4 warps), warp tile 64x64, CTA tile 128x128, TK=64.
// C[M,N] = A[M,K] * B[N,K]^T, A/B fp16 row-major.
// EPI: 0 none, 1 +bias, 2 relu(+bias),
//      3 normalize acc by rowsum[m], +residual res[N,M] (x^T, ld=SS), + stats -> fp32
//      4 +bias +normalize(res[M,N], stats0) residual + stats -> fp32 out
//      5 exp epilogue: c=exp(c*escale), fp16 out, row-partial sums -> atomicAdd rsum
// OUT: 0 fp32 [M,N]; 1 fp16 [M,N]; 2 fp16 transposed [N,M]
#define SKB 144                     // smem row stride in bytes
#define TILE_B (128 * SKB)          // 18432 bytes
#define SMEMB (4 * TILE_B)          // 73728 bytes (2 stages x (A+B)) -> 2 CTAs/SM

template <int EPI, int OUT>
__global__ __launch_bounds__(128)
void gemm_h(const __half* __restrict__ A, const __half* __restrict__ B,
            const float* __restrict__ bias, void* __restrict__ Cv,
            int K, int lda, int ldb, int ldc,
            long long sA, long long sB, long long sC,
            const float* __restrict__ res, long long sR,
            double* __restrict__ stats, const double* __restrict__ stats0,
            float* __restrict__ rsum, float escale)
{
    extern __shared__ char smem[];
    const uint32_t base = smem_u32(smem);

    const int bz = blockIdx.z;
    const __half* Ab = A + (long long)bz * sA;
    const __half* Bb = B + (long long)bz * sB;

    const int m0 = blockIdx.y * 128;
    const int n0 = blockIdx.x * 128;
    const int tid  = threadIdx.x;
    const int lane = tid & 31;
    const int warp = tid >> 5;
    const int wm = (warp >> 1) * 64;   // 0 / 64
    const int wn = (warp & 1) * 64;    // 0 / 64
    const int qr = lane >> 2;   // 0..7
    const int qc = lane & 3;    // 0..3

    float acc[4][8][4];
#pragma unroll
    for (int i = 0; i < 4; i++)
#pragma unroll
        for (int j = 0; j < 8; j++)
#pragma unroll
            for (int q = 0; q < 4; q++) acc[i][j][q] = 0.f;

    const int NKB = K >> 6;

    // staging: each operand tile = 128 rows x 128B; 1024 16B chunks, 8/thread
    const int sx = tid >> 3;       // row 0..15 (+16 per iter)
    const int sc = tid & 7;        // 16B chunk in row
    const uint32_t sdst = (uint32_t)(sx * SKB + sc * 16);

#define STAGE(buf, k0)                                                          \
    do {                                                                        \
        const uint32_t aD = base + (buf) * TILE_B + sdst;                       \
        const uint32_t bD = base + (2 + (buf)) * TILE_B + sdst;                 \
        const __half* aSrc = Ab + (long long)(m0 + sx) * lda + (k0) + sc * 8;   \
        const __half* bSrc = Bb + (long long)(n0 + sx) * ldb + (k0) + sc * 8;   \
        _Pragma("unroll")                                                       \
        for (int it = 0; it < 8; it++) {                                        \
            CP16(aD + it * (16 * SKB), aSrc + (long long)(it * 16) * lda);      \
            CP16(bD + it * (16 * SKB), bSrc + (long long)(it * 16) * ldb);      \
        }                                                                       \
    } while (0)

    STAGE(0, 0);
    CPC();

    // per-lane ldmatrix offsets: lanes 0-15 -> rows (x&15) @ +0B, 16-31 -> @ +16B
    const uint32_t aOff = (uint32_t)((wm + (lane & 15)) * SKB + (lane >> 4) * 16);
    const uint32_t bOff = (uint32_t)((wn + (lane & 15)) * SKB + (lane >> 4) * 16);

    for (int kb = 0; kb < NKB; kb++) {
        const int cur = kb & 1;
        if (kb + 1 < NKB) {
            STAGE(cur ^ 1, (kb + 1) << 6);
            CPC();
            CPW1();
        } else {
            CPW0();
        }
        __syncthreads();

        const uint32_t aT = base + cur * TILE_B + aOff;
        const uint32_t bT = base + (2 + cur) * TILE_B + bOff;
#pragma unroll
        for (int ks = 0; ks < 4; ks++) {
            uint32_t af[4][4], bq[4][4];
#pragma unroll
            for (int mi = 0; mi < 4; mi++)
                LDMX4(af[mi], aT + mi * (16 * SKB) + ks * 32);
#pragma unroll
            for (int ni = 0; ni < 4; ni++)
                LDMX4(bq[ni], bT + ni * (16 * SKB) + ks * 32);
#pragma unroll
            for (int mi = 0; mi < 4; mi++)
#pragma unroll
                for (int ni = 0; ni < 4; ni++) {
                    mma16816(acc[mi][2 * ni],     af[mi], bq[ni][0], bq[ni][2]);
                    mma16816(acc[mi][2 * ni + 1], af[mi], bq[ni][1], bq[ni][3]);
                }
        }
        __syncthreads();
    }
#undef STAGE

    // ---- epilogue ----
    const float* resb = (EPI == 3 || EPI == 4) ? (res + (long long)bz * sR) : nullptr;
    float ls = 0.f, lq = 0.f;
    float nfm = 0.f, ninv = 1.f;
    if (EPI == 4) {
        const double sum = stats0[2 * bz], sq = stats0[2 * bz + 1];
        const double NE = (double)SS * DD;
        const double mean = sum / NE;
        double var = sq - NE * mean * mean;
        if (var < 0.0) var = 0.0;
        ninv = (float)(1.0 / (sqrt(var) + 1e-7));
        nfm  = (float)mean;
    }
    // EPI=3: per-row attention normalization constants
    float zinv0[4], zinv1[4];
    if (EPI == 3) {
#pragma unroll
        for (int mi = 0; mi < 4; mi++) {
            const int m = m0 + wm + mi * 16 + qr;
            zinv0[mi] = 1.f / rsum[(long long)bz * SS + m];
            zinv1[mi] = 1.f / rsum[(long long)bz * SS + m + 8];
        }
    }
    // EPI=5: per-row partial sums of exp
    float rs0[4], rs1[4];
    if (EPI == 5) {
#pragma unroll
        for (int mi = 0; mi < 4; mi++) { rs0[mi] = 0.f; rs1[mi] = 0.f; }
    }

#pragma unroll
    for (int mi = 0; mi < 4; mi++) {
        const int m = m0 + wm + mi * 16 + qr;
#pragma unroll
        for (int ni = 0; ni < 8; ni++) {
            const int nc = n0 + wn + ni * 8 + 2 * qc;
            float c0 = acc[mi][ni][0], c1 = acc[mi][ni][1];
            float c2 = acc[mi][ni][2], c3 = acc[mi][ni][3];
            if (EPI == 1 || EPI == 2 || EPI == 4) {
                const float bx = bias[nc], by = bias[nc + 1];
                c0 += bx; c1 += by; c2 += bx; c3 += by;
            }
            if (EPI == 2) {
                c0 = fmaxf(c0, 0.f); c1 = fmaxf(c1, 0.f);
                c2 = fmaxf(c2, 0.f); c3 = fmaxf(c3, 0.f);
            }
            if (EPI == 3) {
                // normalize by attention row sum, then residual [N, M] (ld = SS)
                c0 = c0 * zinv0[mi] + resb[(long long)nc * SS + m];
                c1 = c1 * zinv0[mi] + resb[(long long)(nc + 1) * SS + m];
                c2 = c2 * zinv1[mi] + resb[(long long)nc * SS + m + 8];
                c3 = c3 * zinv1[mi] + resb[(long long)(nc + 1) * SS + m + 8];
            }
            if (EPI == 4) {
                const float2 r0 = *(const float2*)(resb + (long long)m * DD + nc);
                const float2 r1 = *(const float2*)(resb + (long long)(m + 8) * DD + nc);
                c0 += (r0.x - nfm) * ninv; c1 += (r0.y - nfm) * ninv;
                c2 += (r1.x - nfm) * ninv; c3 += (r1.y - nfm) * ninv;
            }
            if (EPI == 5) {
                c0 = __expf(c0 * escale); c1 = __expf(c1 * escale);
                c2 = __expf(c2 * escale); c3 = __expf(c3 * escale);
                rs0[mi] += c0 + c1;
                rs1[mi] += c2 + c3;
            }
            if (EPI == 3 || EPI == 4) {
                ls += c0 + c1 + c2 + c3;
                lq += c0 * c0 + c1 * c1 + c2 * c2 + c3 * c3;
            }
            if (OUT == 0) {
                float* C = (float*)Cv + (long long)bz * sC;
                float2 lo; lo.x = c0; lo.y = c1;
                float2 hi; hi.x = c2; hi.y = c3;
                *(float2*)(C + (long long)m * ldc + nc) = lo;
                *(float2*)(C + (long long)(m + 8) * ldc + nc) = hi;
            } else if (OUT == 1) {
                __half* C = (__half*)Cv + (long long)bz * sC;
                *(__half2*)(C + (long long)m * ldc + nc) = __floats2half2_rn(c0, c1);
                *(__half2*)(C + (long long)(m + 8) * ldc + nc) = __floats2half2_rn(c2, c3);
            } else {
                __half* C = (__half*)Cv + (long long)bz * sC;
                C[(long long)nc * ldc + m]           = __float2half_rn(c0);
                C[(long long)(nc + 1) * ldc + m]     = __float2half_rn(c1);
                C[(long long)nc * ldc + m + 8]       = __float2half_rn(c2);
                C[(long long)(nc + 1) * ldc + m + 8] = __float2half_rn(c3);
            }
        }
    }

    if (EPI == 5) {
        // reduce row partials across the 4 qc lanes (lane bits 0-1), then atomicAdd
#pragma unroll
        for (int mi = 0; mi < 4; mi++) {
            float a = rs0[mi], b = rs1[mi];
            a += __shfl_xor_sync(0xFFFFFFFFu, a, 1);
            a += __shfl_xor_sync(0xFFFFFFFFu, a, 2);
            b += __shfl_xor_sync(0xFFFFFFFFu, b, 1);
            b += __shfl_xor_sync(0xFFFFFFFFu, b, 2);
            if (qc == 0) {
                const int m = m0 + wm + mi * 16 + qr;
                atomicAdd(rsum + (long long)bz * SS + m, a);
                atomicAdd(rsum + (long long)bz * SS + m + 8, b);
            }
        }
    }

    if (EPI == 3 || EPI == 4) {
        float* sa = (float*)smem;
        float* sb = sa + 128;
        sa[tid] = ls; sb[tid] = lq;
        __syncthreads();
        for (int o = 64; o > 0; o >>= 1) {
            if (tid < o) { sa[tid] += sa[tid + o]; sb[tid] += sb[tid + o]; }
            __syncthreads();
        }
        if (tid == 0) {
            atomicAdd(stats + 2 * bz + 0, (double)sa[0]);
            atomicAdd(stats + 2 * bz + 1, (double)sb[0]);
        }
    }
}

// ---------------- transpose + fp32->fp16 convert: src[R,C] -> dst[C,R] ----------------
__global__ void transpose_h(const float* __restrict__ src, __half* __restrict__ dst,
                            int R, int C)
{
    const int b = blockIdx.z;
    src += (long long)b * R * C;
    dst += (long long)b * R * C;
    const int r0 = blockIdx.y * 32;
    const int c0 = blockIdx.x * 32;
    __shared__ float t[32][33];
    const int tx = threadIdx.x, ty = threadIdx.y;   // 32 x 8
#pragma unroll
    for (int i = 0; i < 32; i += 8)
        t[ty + i][tx] = src[(long long)(r0 + ty + i) * C + c0 + tx];
    __syncthreads();
#pragma unroll
    for (int i = 0; i < 32; i += 8)
        dst[(long long)(c0 + ty + i) * R + r0 + tx] = __float2half_rn(t[tx][ty + i]);
}

// ---------------- straight fp32->fp16 convert ----------------
__global__ void convert_h(const float* __restrict__ src, __half* __restrict__ dst)
{
    const long long i = (long long)blockIdx.x * 256 + threadIdx.x;
    const float4 v = ((const float4*)src)[i];
    __half2* d = (__half2*)dst + i * 2;
    d[0] = __floats2half2_rn(v.x, v.y);
    d[1] = __floats2half2_rn(v.z, v.w);
}

__global__ void zero_acc_kernel()
{
    if (threadIdx.x < 32) g_acc[threadIdx.x] = 0.0;
}

__global__ void zero_rowsum_kernel(float* __restrict__ rs)
{
    rs[blockIdx.x * 256 + threadIdx.x] = 0.f;   // grid = BB*SS/256
}

// read raw y, write ONLY normalized fp16 copy (fp32 y stays raw for EPI=4)
__global__ void apply1h_kernel(const float* __restrict__ y, __half* __restrict__ yh)
{
    const int b = blockIdx.y;
    const double sum = g_acc[2 * b], sq = g_acc[2 * b + 1];
    const double NE = (double)SS * DD;
    const double mean = sum / NE;
    double var = sq - NE * mean * mean;
    if (var < 0.0) var = 0.0;
    const float inv = (float)(1.0 / (sqrt(var) + 1e-7));
    const float fm = (float)mean;

    const float4* y4 = ((const float4*)y) + (long long)b * (SS * DD / 4);
    __half2* yh2 = ((__half2*)yh) + (long long)b * (SS * DD / 2);
    const long long i = (long long)blockIdx.x * 256 + threadIdx.x;  // grid.x = 2048
    float4 vv = y4[i];
    vv.x = (vv.x - fm) * inv; vv.y = (vv.y - fm) * inv;
    vv.z = (vv.z - fm) * inv; vv.w = (vv.w - fm) * inv;
    yh2[i * 2]     = __floats2half2_rn(vv.x, vv.y);
    yh2[i * 2 + 1] = __floats2half2_rn(vv.z, vv.w);
}

// out[b,d,s] = (y2[b,s,d] - mean) * inv
__global__ void apply2t_kernel(const float* __restrict__ y2, float* __restrict__ out)
{
    const int b = blockIdx.z;
    const double sum = g_acc[16 + 2 * b], sq = g_acc[16 + 2 * b + 1];
    const double NE = (double)SS * DD;
    const double mean = sum / NE;
    double var = sq - NE * mean * mean;
    if (var < 0.0) var = 0.0;
    const float inv = (float)(1.0 / (sqrt(var) + 1e-7));
    const float fm = (float)mean;

    const int s0 = blockIdx.x * 32;
    const int d0 = blockIdx.y * 32;
    __shared__ float ys[32][33];
    const int tx = threadIdx.x, ty = threadIdx.y;

#pragma unroll
    for (int i = 0; i < 32; i += 8)
        ys[ty + i][tx] = y2[((long long)b * SS + s0 + ty + i) * DD + d0 + tx];
    __syncthreads();
#pragma unroll
    for (int i = 0; i < 32; i += 8)
        out[((long long)b * DD + d0 + ty + i) * SS + s0 + tx] =
            (ys[tx][ty + i] - fm) * inv;
}

// ---------------- host-side orchestration ----------------
template <typename T>
static T* sym(const void* symbol)
{
    void* p = nullptr;
    cudaGetSymbolAddress(&p, symbol);
    return (T*)p;
}

extern "C" void kernel_launch(void* const* d_in, const int* in_sizes, int n_in,
                              void* d_out, int out_size)
{
    const float* x  = (const float*)d_in[0];
    const float* Wq = (const float*)d_in[1];
    const float* Wk = (const float*)d_in[2];
    const float* Wv = (const float*)d_in[3];
    const float* Wo = (const float*)d_in[4];
    const float* W1 = (const float*)d_in[5];
    const float* b1 = (const float*)d_in[6];
    const float* W2 = (const float*)d_in[7];
    const float* b2 = (const float*)d_in[8];
    float* out = (float*)d_out;

    float*  py    = sym<float>((const void*)g_y);
    float*  ph2   = sym<float>((const void*)g_h2);
    float*  prs   = sym<float>((const void*)g_rowsum);
    double* pacc  = sym<double>((const void*)g_acc);
    __half* pxh   = sym<__half>((const void*)g_xh);
    __half* pqkh  = sym<__half>((const void*)g_qkh);
    __half* pvt   = sym<__half>((const void*)g_vt);
    __half* psh   = sym<__half>((const void*)g_sh);
    __half* pyh   = sym<__half>((const void*)g_yh);
    __half* ph1h  = sym<__half>((const void*)g_h1h);
    __half* pwqkT = sym<__half>((const void*)g_wqkT);
    __half* pwvh  = sym<__half>((const void*)g_wvh);
    __half* pwoT  = sym<__half>((const void*)g_woT);
    __half* pwvoT = sym<__half>((const void*)g_wvoT);
    __half* pw1T  = sym<__half>((const void*)g_w1T);
    __half* pw2T  = sym<__half>((const void*)g_w2T);

    const long long sSD  = (long long)SS * DD;
    const long long sS2D = (long long)SS * 2 * DD;
    const long long sSS  = (long long)SS * SS;
    const long long sSF  = (long long)SS * FF;
    const long long sDS  = (long long)DD * SS;

    cudaFuncSetAttribute(gemm_h<0, 1>, cudaFuncAttributeMaxDynamicSharedMemorySize, SMEMB);
    cudaFuncSetAttribute(gemm_h<0, 2>, cudaFuncAttributeMaxDynamicSharedMemorySize, SMEMB);
    cudaFuncSetAttribute(gemm_h<2, 1>, cudaFuncAttributeMaxDynamicSharedMemorySize, SMEMB);
    cudaFuncSetAttribute(gemm_h<3, 0>, cudaFuncAttributeMaxDynamicSharedMemorySize, SMEMB);
    cudaFuncSetAttribute(gemm_h<4, 0>, cudaFuncAttributeMaxDynamicSharedMemorySize, SMEMB);
    cudaFuncSetAttribute(gemm_h<5, 1>, cudaFuncAttributeMaxDynamicSharedMemorySize, SMEMB);

    zero_acc_kernel<<<1, 32>>>();
    zero_rowsum_kernel<<<BB * SS / 256, 256>>>(prs);

    // pre-pass: fp16 operands
    dim3 tblk(32, 8);
    transpose_h<<<dim3(SS / 32, DD / 32, BB), tblk>>>(x,  pxh,  DD, SS); // x[b]:[D,S]->[S,D]
    transpose_h<<<dim3(DD / 32, DD / 32, 1), tblk>>>(Wq, pwqkT,           DD, DD);
    transpose_h<<<dim3(DD / 32, DD / 32, 1), tblk>>>(Wk, pwqkT + DD * DD, DD, DD);
    transpose_h<<<dim3(DD / 32, DD / 32, 1), tblk>>>(Wo, pwoT, DD, DD);
    convert_h<<<DD * DD / 1024, 256>>>(Wv, pwvh);                        // Wv fp16 (no transpose)
    transpose_h<<<dim3(FF / 32, DD / 32, 1), tblk>>>(W1, pw1T, DD, FF); // [D,F]->[F,D]
    transpose_h<<<dim3(DD / 32, FF / 32, 1), tblk>>>(W2, pw2T, FF, DD); // [F,D]->[D,F]

    dim3 blk(128);
    dim3 gW(DD / 128, DD / 128, 1);          // (4,4,1) weight-product GEMM
    dim3 gQK(2 * DD / 128, SS / 128, BB);    // (8,32,8) merged q|k projection
    dim3 gNarrow(DD / 128, SS / 128, BB);    // (4,32,8)
    dim3 gScore(SS / 128, SS / 128, BB);     // (32,32,8)
    dim3 gFFN(FF / 128, SS / 128, BB);       // (16,32,8)

    // W_voT[m,n] = sum_k WoT[m,k] * Wv[n,k]  ( = (Wv@Wo)^T )
    gemm_h<0, 1><<<gW, blk, SMEMB>>>(pwoT, pwvh, nullptr, pwvoT,
        DD, DD, DD, DD, 0, 0, 0, nullptr, 0, nullptr, nullptr, nullptr, 0.f);

    // qk = xh @ [WqT|WkT]^T  (fp16 out, N=1024 merged)
    gemm_h<0, 1><<<gQK, blk, SMEMB>>>(pxh, pwqkT, nullptr, pqkh,
        DD, DD, DD, 2 * DD, sSD, 0, sS2D, nullptr, 0, nullptr, nullptr, nullptr, 0.f);
    // v' = xh @ (WvWo)^T (fp16 out, transposed to [D,S])
    gemm_h<0, 2><<<gNarrow, blk, SMEMB>>>(pxh, pwvoT, nullptr, pvt,
        DD, DD, DD, SS, sSD, 0, sDS, nullptr, 0, nullptr, nullptr, nullptr, 0.f);

    // e = exp(q @ k^T * scale)  (fp16 out, row sums accumulated into g_rowsum)
    gemm_h<5, 1><<<gScore, blk, SMEMB>>>(pqkh, pqkh + DD, nullptr, psh,
        DD, 2 * DD, 2 * DD, SS, sS2D, sS2D, sSS, nullptr, 0, nullptr, nullptr,
        prs, 0.04419417382415922f /* 1/sqrt(512) */);

    // y = (e @ v') / rowsum + x^T  (fused normalize + residual + stats stage 0)
    gemm_h<3, 0><<<gNarrow, blk, SMEMB>>>(psh, pvt, nullptr, py,
        SS, SS, SS, DD, sSS, sDS, sSD, x, sDS, pacc, nullptr, prs, 0.f);

    apply1h_kernel<<<dim3(2048, BB), 256>>>(py, pyh);

    // FFN
    gemm_h<2, 1><<<gFFN, blk, SMEMB>>>(pyh, pw1T, b1, ph1h,
        DD, DD, DD, FF, sSD, 0, sSF, nullptr, 0, nullptr, nullptr, nullptr, 0.f);
    // h2 = h1 @ W2 + b2 + normalize(y)  (fused residual + stats stage 1, fp32 out)
    gemm_h<4, 0><<<gNarrow, blk, SMEMB>>>(ph1h, pw2T, b2, ph2,
        FF, FF, FF, DD, sSF, 0, sSD, py, sSD, pacc + 16, pacc, nullptr, 0.f);

    apply2t_kernel<<<dim3(SS / 32, DD / 32, BB), tblk>>>(ph2, out);

    (void)in_sizes; (void)n_in; (void)out_size;
}

// round 14
// speedup vs baseline: 1.0873x; 1.0134x over previous
#include <cuda_runtime.h>
#include <cuda_fp16.h>
#include <math.h>
#include <stdint.h>

// Problem constants
#define BB 8
#define DD 512
#define SS 4096
#define FF 2048

// ---------------- static scratch (no allocations allowed) ----------------
// fp32
__device__ float g_y [(size_t)BB * SS * DD];      // raw residual-1 (unnormalized)
__device__ float g_h2[(size_t)BB * SS * DD];
__device__ float g_rowsum[(size_t)BB * SS];       // attention row sums (unnormalized exp)
__device__ double g_acc[32];
// fp16 operands (row-major [x][k] for every GEMM)
__device__ __half g_xh  [(size_t)BB * SS * DD];   // x^T  [B,S,D]
__device__ __half g_qkh [(size_t)BB * SS * 2 * DD]; // [B,S,2D]: q | k
__device__ __half g_vt  [(size_t)BB * DD * SS];   // v'^T [B,D,S]  (v' = x^T Wv Wo)
__device__ __half g_sh  [(size_t)BB * SS * SS];   // unnormalized exp scores, fp16
__device__ __half g_yh  [(size_t)BB * SS * DD];   // normalized post, fp16 copy
__device__ __half g_h1h [(size_t)BB * SS * FF];
__device__ __half g_wqkT[2 * DD * DD];            // [2D, D]: WqT rows 0..511, WkT rows 512..1023
__device__ __half g_wvh [DD * DD];                // Wv fp16, NOT transposed
__device__ __half g_woT [DD * DD];
__device__ __half g_wvoT[DD * DD];                // (Wv@Wo)^T fp16
__device__ __half g_w1T [(size_t)DD * FF];        // [F,D]
__device__ __half g_w2T [(size_t)DD * FF];        // [D,F]

// ---------------- helpers ----------------
__device__ __forceinline__ uint32_t smem_u32(const void* p)
{
    uint32_t a;
    asm("{ .reg .u64 t; cvta.to.shared.u64 t, %1; cvt.u32.u64 %0, t; }" : "=r"(a) : "l"(p));
    return a;
}

#define CP16(d, s) asm volatile("cp.async.ca.shared.global [%0], [%1], 16;" :: "r"(d), "l"(s))
#define CPC()  asm volatile("cp.async.commit_group;" ::: "memory")
#define CPW0() asm volatile("cp.async.wait_group 0;" ::: "memory")
#define CPW1() asm volatile("cp.async.wait_group 1;" ::: "memory")

#define LDMX4(r, addr) \
    asm volatile("ldmatrix.sync.aligned.m8n8.x4.shared.b16 {%0,%1,%2,%3}, [%4];" \
        : "=r"((r)[0]), "=r"((r)[1]), "=r"((r)[2]), "=r"((r)[3]) : "r"(addr))

__device__ __forceinline__ void mma16816(float c[4], const uint32_t a[4],
                                         uint32_t b0, uint32_t b1)
{
    asm volatile(
        "mma.sync.aligned.m16n8k16.row.col.f32.f16.f16.f32 "
        "{%0,%1,%2,%3}, {%4,%5,%6,%7}, {%8,%9}, {%0,%1,%2,%3};\n"
        : "+f"(c[0]), "+f"(c[1]), "+f"(c[2]), "+f"(c[3])
        : "r"(a[0]), "r"(a[1]), "r"(a[2]), "r"(a[3]),
          "r"(b0), "r"(b1));
}

// ---------------- fp16 tensor-core GEMM, 2-stage cp.async + ldmatrix ----------------
// 128 threads (4 warps), warp tile 64x64, CTA tile 128x128, TK=64.
// C[M,N] = A[M,K] * B[N,K]^T, A/B fp16 row-major.
// EPI: 0 none, 1 +bias, 2 relu(+bias),
//      3 normalize acc by rowsum[m], +residual res[N,M] (x^T, ld=SS), + stats -> fp32
//      4 +bias +normalize(res[M,N], stats0) residual + stats -> fp32 out
//      5 exp epilogue: c=exp(c*escale), fp16 out, row-partial sums -> atomicAdd rsum
// OUT: 0 fp32 [M,N]; 1 fp16 [M,N]; 2 fp16 transposed [N,M]
#define SKB 144                     // smem row stride in bytes
#define TILE_B (128 * SKB)          // 18432 bytes
#define SMEMB (4 * TILE_B)          // 73728 bytes (2 stages x (A+B)) -> 2 CTAs/SM

template <int EPI, int OUT>
__global__ __launch_bounds__(128)
void gemm_h(const __half* __restrict__ A, const __half* __restrict__ B,
            const float* __restrict__ bias, void* __restrict__ Cv,
            int K, int lda, int ldb, int ldc,
            long long sA, long long sB, long long sC,
            const float* __restrict__ res, long long sR,
            double* __restrict__ stats, const double* __restrict__ stats0,
            float* __restrict__ rsum, float escale)
{
    extern __shared__ char smem[];
    const uint32_t base = smem_u32(smem);

    const int bz = blockIdx.z;
    const __half* Ab = A + (long long)bz * sA;
    const __half* Bb = B + (long long)bz * sB;

    const int m0 = blockIdx.y * 128;
    const int n0 = blockIdx.x * 128;
    const int tid  = threadIdx.x;
    const int lane = tid & 31;
    const int warp = tid >> 5;
    const int wm = (warp >> 1) * 64;   // 0 / 64
    const int wn = (warp & 1) * 64;    // 0 / 64
    const int qr = lane >> 2;   // 0..7
    const int qc = lane & 3;    // 0..3

    float acc[4][8][4];
#pragma unroll
    for (int i = 0; i < 4; i++)
#pragma unroll
        for (int j = 0; j < 8; j++)
#pragma unroll
            for (int q = 0; q < 4; q++) acc[i][j][q] = 0.f;

    const int NKB = K >> 6;

    // staging: each operand tile = 128 rows x 128B; 1024 16B chunks, 8/thread
    const int sx = tid >> 3;       // row 0..15 (+16 per iter)
    const int sc = tid & 7;        // 16B chunk in row
    const uint32_t sdst = (uint32_t)(sx * SKB + sc * 16);

#define STAGE(buf, k0)                                                          \
    do {                                                                        \
        const uint32_t aD = base + (buf) * TILE_B + sdst;                       \
        const uint32_t bD = base + (2 + (buf)) * TILE_B + sdst;                 \
        const __half* aSrc = Ab + (long long)(m0 + sx) * lda + (k0) + sc * 8;   \
        const __half* bSrc = Bb + (long long)(n0 + sx) * ldb + (k0) + sc * 8;   \
        _Pragma("unroll")                                                       \
        for (int it = 0; it < 8; it++) {                                        \
            CP16(aD + it * (16 * SKB), aSrc + (long long)(it * 16) * lda);      \
            CP16(bD + it * (16 * SKB), bSrc + (long long)(it * 16) * ldb);      \
        }                                                                       \
    } while (0)

    STAGE(0, 0);
    CPC();

    // per-lane ldmatrix offsets: lanes 0-15 -> rows (x&15) @ +0B, 16-31 -> @ +16B
    const uint32_t aOff = (uint32_t)((wm + (lane & 15)) * SKB + (lane >> 4) * 16);
    const uint32_t bOff = (uint32_t)((wn + (lane & 15)) * SKB + (lane >> 4) * 16);

    for (int kb = 0; kb < NKB; kb++) {
        const int cur = kb & 1;
        if (kb + 1 < NKB) {
            STAGE(cur ^ 1, (kb + 1) << 6);
            CPC();
            CPW1();
        } else {
            CPW0();
        }
        __syncthreads();

        const uint32_t aT = base + cur * TILE_B + aOff;
        const uint32_t bT = base + (2 + cur) * TILE_B + bOff;
#pragma unroll
        for (int ks = 0; ks < 4; ks++) {
            uint32_t af[4][4], bq[4][4];
#pragma unroll
            for (int mi = 0; mi < 4; mi++)
                LDMX4(af[mi], aT + mi * (16 * SKB) + ks * 32);
#pragma unroll
            for (int ni = 0; ni < 4; ni++)
                LDMX4(bq[ni], bT + ni * (16 * SKB) + ks * 32);
#pragma unroll
            for (int mi = 0; mi < 4; mi++)
#pragma unroll
                for (int ni = 0; ni < 4; ni++) {
                    mma16816(acc[mi][2 * ni],     af[mi], bq[ni][0], bq[ni][2]);
                    mma16816(acc[mi][2 * ni + 1], af[mi], bq[ni][1], bq[ni][3]);
                }
        }
        __syncthreads();
    }
#undef STAGE

    // ---- epilogue ----
    const float* resb = (EPI == 3 || EPI == 4) ? (res + (long long)bz * sR) : nullptr;
    float ls = 0.f, lq = 0.f;
    float nfm = 0.f, ninv = 1.f;
    if (EPI == 4) {
        const double sum = stats0[2 * bz], sq = stats0[2 * bz + 1];
        const double NE = (double)SS * DD;
        const double mean = sum / NE;
        double var = sq - NE * mean * mean;
        if (var < 0.0) var = 0.0;
        ninv = (float)(1.0 / (sqrt(var) + 1e-7));
        nfm  = (float)mean;
    }
    // EPI=3: per-row attention normalization constants
    float zinv0[4], zinv1[4];
    if (EPI == 3) {
#pragma unroll
        for (int mi = 0; mi < 4; mi++) {
            const int m = m0 + wm + mi * 16 + qr;
            zinv0[mi] = 1.f / rsum[(long long)bz * SS + m];
            zinv1[mi] = 1.f / rsum[(long long)bz * SS + m + 8];
        }
    }
    // EPI=5: per-row partial sums of exp
    float rs0[4], rs1[4];
    if (EPI == 5) {
#pragma unroll
        for (int mi = 0; mi < 4; mi++) { rs0[mi] = 0.f; rs1[mi] = 0.f; }
    }

#pragma unroll
    for (int mi = 0; mi < 4; mi++) {
        const int m = m0 + wm + mi * 16 + qr;
#pragma unroll
        for (int ni = 0; ni < 8; ni++) {
            const int nc = n0 + wn + ni * 8 + 2 * qc;
            float c0 = acc[mi][ni][0], c1 = acc[mi][ni][1];
            float c2 = acc[mi][ni][2], c3 = acc[mi][ni][3];
            if (EPI == 1 || EPI == 2 || EPI == 4) {
                const float bx = bias[nc], by = bias[nc + 1];
                c0 += bx; c1 += by; c2 += bx; c3 += by;
            }
            if (EPI == 2) {
                c0 = fmaxf(c0, 0.f); c1 = fmaxf(c1, 0.f);
                c2 = fmaxf(c2, 0.f); c3 = fmaxf(c3, 0.f);
            }
            if (EPI == 3) {
                // normalize by attention row sum, then residual [N, M] (ld = SS)
                c0 = c0 * zinv0[mi] + resb[(long long)nc * SS + m];
                c1 = c1 * zinv0[mi] + resb[(long long)(nc + 1) * SS + m];
                c2 = c2 * zinv1[mi] + resb[(long long)nc * SS + m + 8];
                c3 = c3 * zinv1[mi] + resb[(long long)(nc + 1) * SS + m + 8];
            }
            if (EPI == 4) {
                const float2 r0 = *(const float2*)(resb + (long long)m * DD + nc);
                const float2 r1 = *(const float2*)(resb + (long long)(m + 8) * DD + nc);
                c0 += (r0.x - nfm) * ninv; c1 += (r0.y - nfm) * ninv;
                c2 += (r1.x - nfm) * ninv; c3 += (r1.y - nfm) * ninv;
            }
            if (EPI == 5) {
                c0 = __expf(c0 * escale); c1 = __expf(c1 * escale);
                c2 = __expf(c2 * escale); c3 = __expf(c3 * escale);
                rs0[mi] += c0 + c1;
                rs1[mi] += c2 + c3;
            }
            if (EPI == 3 || EPI == 4) {
                ls += c0 + c1 + c2 + c3;
                lq += c0 * c0 + c1 * c1 + c2 * c2 + c3 * c3;
            }
            if (OUT == 0) {
                float* C = (float*)Cv + (long long)bz * sC;
                float2 lo; lo.x = c0; lo.y = c1;
                float2 hi; hi.x = c2; hi.y = c3;
                *(float2*)(C + (long long)m * ldc + nc) = lo;
                *(float2*)(C + (long long)(m + 8) * ldc + nc) = hi;
            } else if (OUT == 1) {
                __half* C = (__half*)Cv + (long long)bz * sC;
                *(__half2*)(C + (long long)m * ldc + nc) = __floats2half2_rn(c0, c1);
                *(__half2*)(C + (long long)(m + 8) * ldc + nc) = __floats2half2_rn(c2, c3);
            } else {
                __half* C = (__half*)Cv + (long long)bz * sC;
                C[(long long)nc * ldc + m]           = __float2half_rn(c0);
                C[(long long)(nc + 1) * ldc + m]     = __float2half_rn(c1);
                C[(long long)nc * ldc + m + 8]       = __float2half_rn(c2);
                C[(long long)(nc + 1) * ldc + m + 8] = __float2half_rn(c3);
            }
        }
    }

    if (EPI == 5) {
        // reduce row partials across the 4 qc lanes (lane bits 0-1), then atomicAdd
#pragma unroll
        for (int mi = 0; mi < 4; mi++) {
            float a = rs0[mi], b = rs1[mi];
            a += __shfl_xor_sync(0xFFFFFFFFu, a, 1);
            a += __shfl_xor_sync(0xFFFFFFFFu, a, 2);
            b += __shfl_xor_sync(0xFFFFFFFFu, b, 1);
            b += __shfl_xor_sync(0xFFFFFFFFu, b, 2);
            if (qc == 0) {
                const int m = m0 + wm + mi * 16 + qr;
                atomicAdd(rsum + (long long)bz * SS + m, a);
                atomicAdd(rsum + (long long)bz * SS + m + 8, b);
            }
        }
    }

    if (EPI == 3 || EPI == 4) {
        float* sa = (float*)smem;
        float* sb = sa + 128;
        sa[tid] = ls; sb[tid] = lq;
        __syncthreads();
        for (int o = 64; o > 0; o >>= 1) {
            if (tid < o) { sa[tid] += sa[tid + o]; sb[tid] += sb[tid + o]; }
            __syncthreads();
        }
        if (tid == 0) {
            atomicAdd(stats + 2 * bz + 0, (double)sa[0]);
            atomicAdd(stats + 2 * bz + 1, (double)sb[0]);
        }
    }
}

// ---------------- transpose + fp32->fp16 convert: src[R,C] -> dst[C,R] ----------------
__global__ void transpose_h(const float* __restrict__ src, __half* __restrict__ dst,
                            int R, int C)
{
    const int b = blockIdx.z;
    src += (long long)b * R * C;
    dst += (long long)b * R * C;
    const int r0 = blockIdx.y * 32;
    const int c0 = blockIdx.x * 32;
    __shared__ float t[32][33];
    const int tx = threadIdx.x, ty = threadIdx.y;   // 32 x 8
#pragma unroll
    for (int i = 0; i < 32; i += 8)
        t[ty + i][tx] = src[(long long)(r0 + ty + i) * C + c0 + tx];
    __syncthreads();
#pragma unroll
    for (int i = 0; i < 32; i += 8)
        dst[(long long)(c0 + ty + i) * R + r0 + tx] = __float2half_rn(t[tx][ty + i]);
}

// ---------------- straight fp32->fp16 convert ----------------
__global__ void convert_h(const float* __restrict__ src, __half* __restrict__ dst)
{
    const long long i = (long long)blockIdx.x * 256 + threadIdx.x;
    const float4 v = ((const float4*)src)[i];
    __half2* d = (__half2*)dst + i * 2;
    d[0] = __floats2half2_rn(v.x, v.y);
    d[1] = __floats2half2_rn(v.z, v.w);
}

// zero g_acc + g_rowsum in one launch (grid = BB*SS/256)
__global__ void zero_all_kernel(float* __restrict__ rs)
{
    const int i = blockIdx.x * 256 + threadIdx.x;
    rs[i] = 0.f;
    if (blockIdx.x == 0 && threadIdx.x < 32) g_acc[threadIdx.x] = 0.0;
}

// read raw y, write ONLY normalized fp16 copy (fp32 y stays raw for EPI=4)
__global__ void apply1h_kernel(const float* __restrict__ y, __half* __restrict__ yh)
{
    const int b = blockIdx.y;
    const double sum = g_acc[2 * b], sq = g_acc[2 * b + 1];
    const double NE = (double)SS * DD;
    const double mean = sum / NE;
    double var = sq - NE * mean * mean;
    if (var < 0.0) var = 0.0;
    const float inv = (float)(1.0 / (sqrt(var) + 1e-7));
    const float fm = (float)mean;

    const float4* y4 = ((const float4*)y) + (long long)b * (SS * DD / 4);
    __half2* yh2 = ((__half2*)yh) + (long long)b * (SS * DD / 2);
    const long long i = (long long)blockIdx.x * 256 + threadIdx.x;  // grid.x = 2048
    float4 vv = y4[i];
    vv.x = (vv.x - fm) * inv; vv.y = (vv.y - fm) * inv;
    vv.z = (vv.z - fm) * inv; vv.w = (vv.w - fm) * inv;
    yh2[i * 2]     = __floats2half2_rn(vv.x, vv.y);
    yh2[i * 2 + 1] = __floats2half2_rn(vv.z, vv.w);
}

// out[b,d,s] = (y2[b,s,d] - mean) * inv
__global__ void apply2t_kernel(const float* __restrict__ y2, float* __restrict__ out)
{
    const int b = blockIdx.z;
    const double sum = g_acc[16 + 2 * b], sq = g_acc[16 + 2 * b + 1];
    const double NE = (double)SS * DD;
    const double mean = sum / NE;
    double var = sq - NE * mean * mean;
    if (var < 0.0) var = 0.0;
    const float inv = (float)(1.0 / (sqrt(var) + 1e-7));
    const float fm = (float)mean;

    const int s0 = blockIdx.x * 32;
    const int d0 = blockIdx.y * 32;
    __shared__ float ys[32][33];
    const int tx = threadIdx.x, ty = threadIdx.y;

#pragma unroll
    for (int i = 0; i < 32; i += 8)
        ys[ty + i][tx] = y2[((long long)b * SS + s0 + ty + i) * DD + d0 + tx];
    __syncthreads();
#pragma unroll
    for (int i = 0; i < 32; i += 8)
        out[((long long)b * DD + d0 + ty + i) * SS + s0 + tx] =
            (ys[tx][ty + i] - fm) * inv;
}

// ---------------- host-side orchestration ----------------
template <typename T>
static T* sym(const void* symbol)
{
    void* p = nullptr;
    cudaGetSymbolAddress(&p, symbol);
    return (T*)p;
}

extern "C" void kernel_launch(void* const* d_in, const int* in_sizes, int n_in,
                              void* d_out, int out_size)
{
    const float* x  = (const float*)d_in[0];
    const float* Wq = (const float*)d_in[1];
    const float* Wk = (const float*)d_in[2];
    const float* Wv = (const float*)d_in[3];
    const float* Wo = (const float*)d_in[4];
    const float* W1 = (const float*)d_in[5];
    const float* b1 = (const float*)d_in[6];
    const float* W2 = (const float*)d_in[7];
    const float* b2 = (const float*)d_in[8];
    float* out = (float*)d_out;

    float*  py    = sym<float>((const void*)g_y);
    float*  ph2   = sym<float>((const void*)g_h2);
    float*  prs   = sym<float>((const void*)g_rowsum);
    double* pacc  = sym<double>((const void*)g_acc);
    __half* pxh   = sym<__half>((const void*)g_xh);
    __half* pqkh  = sym<__half>((const void*)g_qkh);
    __half* pvt   = sym<__half>((const void*)g_vt);
    __half* psh   = sym<__half>((const void*)g_sh);
    __half* pyh   = sym<__half>((const void*)g_yh);
    __half* ph1h  = sym<__half>((const void*)g_h1h);
    __half* pwqkT = sym<__half>((const void*)g_wqkT);
    __half* pwvh  = sym<__half>((const void*)g_wvh);
    __half* pwoT  = sym<__half>((const void*)g_woT);
    __half* pwvoT = sym<__half>((const void*)g_wvoT);
    __half* pw1T  = sym<__half>((const void*)g_w1T);
    __half* pw2T  = sym<__half>((const void*)g_w2T);

    const long long sSD  = (long long)SS * DD;
    const long long sS2D = (long long)SS * 2 * DD;
    const long long sSS  = (long long)SS * SS;
    const long long sSF  = (long long)SS * FF;
    const long long sDS  = (long long)DD * SS;

    cudaFuncSetAttribute(gemm_h<0, 1>, cudaFuncAttributeMaxDynamicSharedMemorySize, SMEMB);
    cudaFuncSetAttribute(gemm_h<0, 2>, cudaFuncAttributeMaxDynamicSharedMemorySize, SMEMB);
    cudaFuncSetAttribute(gemm_h<2, 1>, cudaFuncAttributeMaxDynamicSharedMemorySize, SMEMB);
    cudaFuncSetAttribute(gemm_h<3, 0>, cudaFuncAttributeMaxDynamicSharedMemorySize, SMEMB);
    cudaFuncSetAttribute(gemm_h<4, 0>, cudaFuncAttributeMaxDynamicSharedMemorySize, SMEMB);
    cudaFuncSetAttribute(gemm_h<5, 1>, cudaFuncAttributeMaxDynamicSharedMemorySize, SMEMB);

    // static side streams + events (created once, outside any capture)
    static cudaStream_t s1 = nullptr, s2 = nullptr;
    static cudaEvent_t evFork = nullptr, evX = nullptr, evV = nullptr, evW = nullptr;
    if (s1 == nullptr) {
        cudaStreamCreateWithFlags(&s1, cudaStreamNonBlocking);
        cudaStreamCreateWithFlags(&s2, cudaStreamNonBlocking);
        cudaEventCreateWithFlags(&evFork, cudaEventDisableTiming);
        cudaEventCreateWithFlags(&evX, cudaEventDisableTiming);
        cudaEventCreateWithFlags(&evV, cudaEventDisableTiming);
        cudaEventCreateWithFlags(&evW, cudaEventDisableTiming);
    }

    dim3 tblk(32, 8);
    dim3 blk(128);
    dim3 gW(DD / 128, DD / 128, 1);          // (4,4,1) weight-product GEMM
    dim3 gQK(2 * DD / 128, SS / 128, BB);    // (8,32,8) merged q|k projection
    dim3 gNarrow(DD / 128, SS / 128, BB);    // (4,32,8)
    dim3 gScore(SS / 128, SS / 128, BB);     // (32,32,8)
    dim3 gFFN(FF / 128, SS / 128, BB);       // (16,32,8)

    // ---- main stream: zero + x transpose + q/k weights ----
    zero_all_kernel<<<BB * SS / 256, 256>>>(prs);
    cudaEventRecord(evFork, 0);              // fork point for W1/W2 branch

    transpose_h<<<dim3(SS / 32, DD / 32, BB), tblk>>>(x, pxh, DD, SS);
    cudaEventRecord(evX, 0);                 // xh ready (for v' branch)

    transpose_h<<<dim3(DD / 32, DD / 32, 1), tblk>>>(Wq, pwqkT,           DD, DD);
    transpose_h<<<dim3(DD / 32, DD / 32, 1), tblk>>>(Wk, pwqkT + DD * DD, DD, DD);

    // ---- side stream s1: Wo/Wv prep, WvWo product, v' projection ----
    cudaStreamWaitEvent(s1, evX, 0);
    transpose_h<<<dim3(DD / 32, DD / 32, 1), tblk, 0, s1>>>(Wo, pwoT, DD, DD);
    convert_h<<<DD * DD / 1024, 256, 0, s1>>>(Wv, pwvh);
    gemm_h<0, 1><<<gW, blk, SMEMB, s1>>>(pwoT, pwvh, nullptr, pwvoT,
        DD, DD, DD, DD, 0, 0, 0, nullptr, 0, nullptr, nullptr, nullptr, 0.f);
    gemm_h<0, 2><<<gNarrow, blk, SMEMB, s1>>>(pxh, pwvoT, nullptr, pvt,
        DD, DD, DD, SS, sSD, 0, sDS, nullptr, 0, nullptr, nullptr, nullptr, 0.f);
    cudaEventRecord(evV, s1);

    // ---- side stream s2: FFN weight transposes ----
    cudaStreamWaitEvent(s2, evFork, 0);
    transpose_h<<<dim3(FF / 32, DD / 32, 1), tblk, 0, s2>>>(W1, pw1T, DD, FF);
    transpose_h<<<dim3(DD / 32, FF / 32, 1), tblk, 0, s2>>>(W2, pw2T, FF, DD);
    cudaEventRecord(evW, s2);

    // ---- main stream: attention chain ----
    // qk = xh @ [WqT|WkT]^T  (fp16 out, N=1024 merged)
    gemm_h<0, 1><<<gQK, blk, SMEMB>>>(pxh, pwqkT, nullptr, pqkh,
        DD, DD, DD, 2 * DD, sSD, 0, sS2D, nullptr, 0, nullptr, nullptr, nullptr, 0.f);

    // e = exp(q @ k^T * scale)  (fp16 out, row sums accumulated into g_rowsum)
    gemm_h<5, 1><<<gScore, blk, SMEMB>>>(pqkh, pqkh + DD, nullptr, psh,
        DD, 2 * DD, 2 * DD, SS, sS2D, sS2D, sSS, nullptr, 0, nullptr, nullptr,
        prs, 0.04419417382415922f /* 1/sqrt(512) */);

    // join v' branch, then AV GEMM
    cudaStreamWaitEvent(0, evV, 0);
    // y = (e @ v') / rowsum + x^T  (fused normalize + residual + stats stage 0)
    gemm_h<3, 0><<<gNarrow, blk, SMEMB>>>(psh, pvt, nullptr, py,
        SS, SS, SS, DD, sSS, sDS, sSD, x, sDS, pacc, nullptr, prs, 0.f);

    apply1h_kernel<<<dim3(2048, BB), 256>>>(py, pyh);

    // join W1/W2 branch, then FFN
    cudaStreamWaitEvent(0, evW, 0);
    gemm_h<2, 1><<<gFFN, blk, SMEMB>>>(pyh, pw1T, b1, ph1h,
        DD, DD, DD, FF, sSD, 0, sSF, nullptr, 0, nullptr, nullptr, nullptr, 0.f);
    // h2 = h1 @ W2 + b2 + normalize(y)  (fused residual + stats stage 1, fp32 out)
    gemm_h<4, 0><<<gNarrow, blk, SMEMB>>>(ph1h, pw2T, b2, ph2,
        FF, FF, FF, DD, sSF, 0, sSD, py, sSD, pacc + 16, pacc, nullptr, 0.f);

    apply2t_kernel<<<dim3(SS / 32, DD / 32, BB), tblk>>>(ph2, out);

    (void)in_sizes; (void)n_in; (void)out_size;
}

// round 15
// speedup vs baseline: 1.0912x; 1.0036x over previous
#include <cuda_runtime.h>
#include <cuda_fp16.h>
#include <math.h>
#include <stdint.h>

// Problem constants
#define BB 8
#define DD 512
#define SS 4096
#define FF 2048

// ---------------- static scratch (no allocations allowed) ----------------
// fp32
__device__ float g_y [(size_t)BB * SS * DD];      // raw residual-1 (unnormalized)
__device__ float g_h2[(size_t)BB * SS * DD];
__device__ float g_rowsum[(size_t)BB * SS];       // attention row sums (unnormalized exp)
__device__ double g_acc[32];
// fp16 operands (row-major [x][k] for every GEMM)
__device__ __half g_xh  [(size_t)BB * SS * DD];   // x^T  [B,S,D]
__device__ __half g_qkh [(size_t)BB * SS * 2 * DD]; // [B,S,2D]: q | k
__device__ __half g_vt  [(size_t)BB * DD * SS];   // v'^T [B,D,S]  (v' = x^T Wv Wo)
__device__ __half g_sh  [(size_t)BB * SS * SS];   // unnormalized exp scores, fp16
__device__ __half g_yh  [(size_t)BB * SS * DD];   // normalized post, fp16 copy
__device__ __half g_h1h [(size_t)BB * SS * FF];
__device__ __half g_wqkT[2 * DD * DD];            // [2D, D]: WqT rows 0..511, WkT rows 512..1023
__device__ __half g_wvh [DD * DD];                // Wv fp16, NOT transposed
__device__ __half g_woT [DD * DD];
__device__ __half g_wvoT[DD * DD];                // (Wv@Wo)^T fp16
__device__ __half g_w1T [(size_t)DD * FF];        // [F,D]
__device__ __half g_w2T [(size_t)DD * FF];        // [D,F]

// ---------------- helpers ----------------
__device__ __forceinline__ uint32_t smem_u32(const void* p)
{
    uint32_t a;
    asm("{ .reg .u64 t; cvta.to.shared.u64 t, %1; cvt.u32.u64 %0, t; }" : "=r"(a) : "l"(p));
    return a;
}

#define CP16(d, s) asm volatile("cp.async.ca.shared.global [%0], [%1], 16;" :: "r"(d), "l"(s))
#define CPC()  asm volatile("cp.async.commit_group;" ::: "memory")
#define CPW0() asm volatile("cp.async.wait_group 0;" ::: "memory")
#define CPW1() asm volatile("cp.async.wait_group 1;" ::: "memory")

#define LDMX4(r, addr) \
    asm volatile("ldmatrix.sync.aligned.m8n8.x4.shared.b16 {%0,%1,%2,%3}, [%4];" \
        : "=r"((r)[0]), "=r"((r)[1]), "=r"((r)[2]), "=r"((r)[3]) : "r"(addr))

__device__ __forceinline__ void mma16816(float c[4], const uint32_t a[4],
                                         uint32_t b0, uint32_t b1)
{
    asm volatile(
        "mma.sync.aligned.m16n8k16.row.col.f32.f16.f16.f32 "
        "{%0,%1,%2,%3}, {%4,%5,%6,%7}, {%8,%9}, {%0,%1,%2,%3};\n"
        : "+f"(c[0]), "+f"(c[1]), "+f"(c[2]), "+f"(c[3])
        : "r"(a[0]), "r"(a[1]), "r"(a[2]), "r"(a[3]),
          "r"(b0), "r"(b1));
}

// packed half2 2^x approximation (one MUFU per two values)
__device__ __forceinline__ uint32_t ex2_f16x2(uint32_t u)
{
    asm("ex2.approx.f16x2 %0, %0;" : "+r"(u));
    return u;
}

// ---------------- fp16 tensor-core GEMM, 2-stage cp.async + ldmatrix ----------------
// 128 threads (4 warps), warp tile 64x64, CTA tile 128x128, TK=64.
// C[M,N] = A[M,K] * B[N,K]^T, A/B fp16 row-major.
// EPI: 0 none, 1 +bias, 2 relu(+bias),
//      3 normalize acc by rowsum[m], +residual res[N,M] (x^T, ld=SS), + stats -> fp32
//      4 +bias +normalize(res[M,N], stats0) residual + stats -> fp32 out
//      5 exp2 epilogue: c=2^(c*escale) via ex2.approx.f16x2, fp16 out,
//        row sums (of the stored fp16 values) -> atomicAdd rsum
// OUT: 0 fp32 [M,N]; 1 fp16 [M,N]; 2 fp16 transposed [N,M]
#define SKB 144                     // smem row stride in bytes
#define TILE_B (128 * SKB)          // 18432 bytes
#define SMEMB (4 * TILE_B)          // 73728 bytes (2 stages x (A+B)) -> 2 CTAs/SM

template <int EPI, int OUT>
__global__ __launch_bounds__(128)
void gemm_h(const __half* __restrict__ A, const __half* __restrict__ B,
            const float* __restrict__ bias, void* __restrict__ Cv,
            int K, int lda, int ldb, int ldc,
            long long sA, long long sB, long long sC,
            const float* __restrict__ res, long long sR,
            double* __restrict__ stats, const double* __restrict__ stats0,
            float* __restrict__ rsum, float escale)
{
    extern __shared__ char smem[];
    const uint32_t base = smem_u32(smem);

    const int bz = blockIdx.z;
    const __half* Ab = A + (long long)bz * sA;
    const __half* Bb = B + (long long)bz * sB;

    const int m0 = blockIdx.y * 128;
    const int n0 = blockIdx.x * 128;
    const int tid  = threadIdx.x;
    const int lane = tid & 31;
    const int warp = tid >> 5;
    const int wm = (warp >> 1) * 64;   // 0 / 64
    const int wn = (warp & 1) * 64;    // 0 / 64
    const int qr = lane >> 2;   // 0..7
    const int qc = lane & 3;    // 0..3

    float acc[4][8][4];
#pragma unroll
    for (int i = 0; i < 4; i++)
#pragma unroll
        for (int j = 0; j < 8; j++)
#pragma unroll
            for (int q = 0; q < 4; q++) acc[i][j][q] = 0.f;

    const int NKB = K >> 6;

    // staging: each operand tile = 128 rows x 128B; 1024 16B chunks, 8/thread
    const int sx = tid >> 3;       // row 0..15 (+16 per iter)
    const int sc = tid & 7;        // 16B chunk in row
    const uint32_t sdst = (uint32_t)(sx * SKB + sc * 16);

#define STAGE(buf, k0)                                                          \
    do {                                                                        \
        const uint32_t aD = base + (buf) * TILE_B + sdst;                       \
        const uint32_t bD = base + (2 + (buf)) * TILE_B + sdst;                 \
        const __half* aSrc = Ab + (long long)(m0 + sx) * lda + (k0) + sc * 8;   \
        const __half* bSrc = Bb + (long long)(n0 + sx) * ldb + (k0) + sc * 8;   \
        _Pragma("unroll")                                                       \
        for (int it = 0; it < 8; it++) {                                        \
            CP16(aD + it * (16 * SKB), aSrc + (long long)(it * 16) * lda);      \
            CP16(bD + it * (16 * SKB), bSrc + (long long)(it * 16) * ldb);      \
        }                                                                       \
    } while (0)

    STAGE(0, 0);
    CPC();

    // per-lane ldmatrix offsets: lanes 0-15 -> rows (x&15) @ +0B, 16-31 -> @ +16B
    const uint32_t aOff = (uint32_t)((wm + (lane & 15)) * SKB + (lane >> 4) * 16);
    const uint32_t bOff = (uint32_t)((wn + (lane & 15)) * SKB + (lane >> 4) * 16);

    for (int kb = 0; kb < NKB; kb++) {
        const int cur = kb & 1;
        if (kb + 1 < NKB) {
            STAGE(cur ^ 1, (kb + 1) << 6);
            CPC();
            CPW1();
        } else {
            CPW0();
        }
        __syncthreads();

        const uint32_t aT = base + cur * TILE_B + aOff;
        const uint32_t bT = base + (2 + cur) * TILE_B + bOff;
#pragma unroll
        for (int ks = 0; ks < 4; ks++) {
            uint32_t af[4][4], bq[4][4];
#pragma unroll
            for (int mi = 0; mi < 4; mi++)
                LDMX4(af[mi], aT + mi * (16 * SKB) + ks * 32);
#pragma unroll
            for (int ni = 0; ni < 4; ni++)
                LDMX4(bq[ni], bT + ni * (16 * SKB) + ks * 32);
#pragma unroll
            for (int mi = 0; mi < 4; mi++)
#pragma unroll
                for (int ni = 0; ni < 4; ni++) {
                    mma16816(acc[mi][2 * ni],     af[mi], bq[ni][0], bq[ni][2]);
                    mma16816(acc[mi][2 * ni + 1], af[mi], bq[ni][1], bq[ni][3]);
                }
        }
        __syncthreads();
    }
#undef STAGE

    // ---- epilogue ----
    const float* resb = (EPI == 3 || EPI == 4) ? (res + (long long)bz * sR) : nullptr;
    float ls = 0.f, lq = 0.f;
    float nfm = 0.f, ninv = 1.f;
    if (EPI == 4) {
        const double sum = stats0[2 * bz], sq = stats0[2 * bz + 1];
        const double NE = (double)SS * DD;
        const double mean = sum / NE;
        double var = sq - NE * mean * mean;
        if (var < 0.0) var = 0.0;
        ninv = (float)(1.0 / (sqrt(var) + 1e-7));
        nfm  = (float)mean;
    }
    // EPI=3: per-row attention normalization constants
    float zinv0[4], zinv1[4];
    if (EPI == 3) {
#pragma unroll
        for (int mi = 0; mi < 4; mi++) {
            const int m = m0 + wm + mi * 16 + qr;
            zinv0[mi] = 1.f / rsum[(long long)bz * SS + m];
            zinv1[mi] = 1.f / rsum[(long long)bz * SS + m + 8];
        }
    }
    // EPI=5: per-row partial sums of exp
    float rs0[4], rs1[4];
    if (EPI == 5) {
#pragma unroll
        for (int mi = 0; mi < 4; mi++) { rs0[mi] = 0.f; rs1[mi] = 0.f; }
    }

#pragma unroll
    for (int mi = 0; mi < 4; mi++) {
        const int m = m0 + wm + mi * 16 + qr;
#pragma unroll
        for (int ni = 0; ni < 8; ni++) {
            const int nc = n0 + wn + ni * 8 + 2 * qc;
            float c0 = acc[mi][ni][0], c1 = acc[mi][ni][1];
            float c2 = acc[mi][ni][2], c3 = acc[mi][ni][3];

            if (EPI == 5) {
                // e = 2^(c * escale) on packed half2 (escale includes log2(e)/sqrt(D))
                __half2 h01 = __floats2half2_rn(c0 * escale, c1 * escale);
                __half2 h23 = __floats2half2_rn(c2 * escale, c3 * escale);
                uint32_t u01 = ex2_f16x2(*(const uint32_t*)&h01);
                uint32_t u23 = ex2_f16x2(*(const uint32_t*)&h23);
                __half* C = (__half*)Cv + (long long)bz * sC;
                *(uint32_t*)(C + (long long)m * ldc + nc)       = u01;
                *(uint32_t*)(C + (long long)(m + 8) * ldc + nc) = u23;
                const float2 f01 = __half22float2(*(const __half2*)&u01);
                const float2 f23 = __half22float2(*(const __half2*)&u23);
                rs0[mi] += f01.x + f01.y;
                rs1[mi] += f23.x + f23.y;
                continue;
            }

            if (EPI == 1 || EPI == 2 || EPI == 4) {
                const float bx = bias[nc], by = bias[nc + 1];
                c0 += bx; c1 += by; c2 += bx; c3 += by;
            }
            if (EPI == 2) {
                c0 = fmaxf(c0, 0.f); c1 = fmaxf(c1, 0.f);
                c2 = fmaxf(c2, 0.f); c3 = fmaxf(c3, 0.f);
            }
            if (EPI == 3) {
                // normalize by attention row sum, then residual [N, M] (ld = SS)
                c0 = c0 * zinv0[mi] + resb[(long long)nc * SS + m];
                c1 = c1 * zinv0[mi] + resb[(long long)(nc + 1) * SS + m];
                c2 = c2 * zinv1[mi] + resb[(long long)nc * SS + m + 8];
                c3 = c3 * zinv1[mi] + resb[(long long)(nc + 1) * SS + m + 8];
            }
            if (EPI == 4) {
                const float2 r0 = *(const float2*)(resb + (long long)m * DD + nc);
                const float2 r1 = *(const float2*)(resb + (long long)(m + 8) * DD + nc);
                c0 += (r0.x - nfm) * ninv; c1 += (r0.y - nfm) * ninv;
                c2 += (r1.x - nfm) * ninv; c3 += (r1.y - nfm) * ninv;
            }
            if (EPI == 3 || EPI == 4) {
                ls += c0 + c1 + c2 + c3;
                lq += c0 * c0 + c1 * c1 + c2 * c2 + c3 * c3;
            }
            if (OUT == 0) {
                float* C = (float*)Cv + (long long)bz * sC;
                float2 lo; lo.x = c0; lo.y = c1;
                float2 hi; hi.x = c2; hi.y = c3;
                *(float2*)(C + (long long)m * ldc + nc) = lo;
                *(float2*)(C + (long long)(m + 8) * ldc + nc) = hi;
            } else if (OUT == 1) {
                __half* C = (__half*)Cv + (long long)bz * sC;
                *(__half2*)(C + (long long)m * ldc + nc) = __floats2half2_rn(c0, c1);
                *(__half2*)(C + (long long)(m + 8) * ldc + nc) = __floats2half2_rn(c2, c3);
            } else {
                __half* C = (__half*)Cv + (long long)bz * sC;
                C[(long long)nc * ldc + m]           = __float2half_rn(c0);
                C[(long long)(nc + 1) * ldc + m]     = __float2half_rn(c1);
                C[(long long)nc * ldc + m + 8]       = __float2half_rn(c2);
                C[(long long)(nc + 1) * ldc + m + 8] = __float2half_rn(c3);
            }
        }
    }

    if (EPI == 5) {
        // reduce row partials across the 4 qc lanes (lane bits 0-1), then atomicAdd
#pragma unroll
        for (int mi = 0; mi < 4; mi++) {
            float a = rs0[mi], b = rs1[mi];
            a += __shfl_xor_sync(0xFFFFFFFFu, a, 1);
            a += __shfl_xor_sync(0xFFFFFFFFu, a, 2);
            b += __shfl_xor_sync(0xFFFFFFFFu, b, 1);
            b += __shfl_xor_sync(0xFFFFFFFFu, b, 2);
            if (qc == 0) {
                const int m = m0 + wm + mi * 16 + qr;
                atomicAdd(rsum + (long long)bz * SS + m, a);
                atomicAdd(rsum + (long long)bz * SS + m + 8, b);
            }
        }
    }

    if (EPI == 3 || EPI == 4) {
        float* sa = (float*)smem;
        float* sb = sa + 128;
        sa[tid] = ls; sb[tid] = lq;
        __syncthreads();
        for (int o = 64; o > 0; o >>= 1) {
            if (tid < o) { sa[tid] += sa[tid + o]; sb[tid] += sb[tid + o]; }
            __syncthreads();
        }
        if (tid == 0) {
            atomicAdd(stats + 2 * bz + 0, (double)sa[0]);
            atomicAdd(stats + 2 * bz + 1, (double)sb[0]);
        }
    }
}

// ---------------- transpose + fp32->fp16 convert: src[R,C] -> dst[C,R] ----------------
__global__ void transpose_h(const float* __restrict__ src, __half* __restrict__ dst,
                            int R, int C)
{
    const int b = blockIdx.z;
    src += (long long)b * R * C;
    dst += (long long)b * R * C;
    const int r0 = blockIdx.y * 32;
    const int c0 = blockIdx.x * 32;
    __shared__ float t[32][33];
    const int tx = threadIdx.x, ty = threadIdx.y;   // 32 x 8
#pragma unroll
    for (int i = 0; i < 32; i += 8)
        t[ty + i][tx] = src[(long long)(r0 + ty + i) * C + c0 + tx];
    __syncthreads();
#pragma unroll
    for (int i = 0; i < 32; i += 8)
        dst[(long long)(c0 + ty + i) * R + r0 + tx] = __float2half_rn(t[tx][ty + i]);
}

// ---------------- straight fp32->fp16 convert ----------------
__global__ void convert_h(const float* __restrict__ src, __half* __restrict__ dst)
{
    const long long i = (long long)blockIdx.x * 256 + threadIdx.x;
    const float4 v = ((const float4*)src)[i];
    __half2* d = (__half2*)dst + i * 2;
    d[0] = __floats2half2_rn(v.x, v.y);
    d[1] = __floats2half2_rn(v.z, v.w);
}

// zero g_acc + g_rowsum in one launch (grid = BB*SS/256)
__global__ void zero_all_kernel(float* __restrict__ rs)
{
    const int i = blockIdx.x * 256 + threadIdx.x;
    rs[i] = 0.f;
    if (blockIdx.x == 0 && threadIdx.x < 32) g_acc[threadIdx.x] = 0.0;
}

// read raw y, write ONLY normalized fp16 copy (fp32 y stays raw for EPI=4)
__global__ void apply1h_kernel(const float* __restrict__ y, __half* __restrict__ yh)
{
    const int b = blockIdx.y;
    const double sum = g_acc[2 * b], sq = g_acc[2 * b + 1];
    const double NE = (double)SS * DD;
    const double mean = sum / NE;
    double var = sq - NE * mean * mean;
    if (var < 0.0) var = 0.0;
    const float inv = (float)(1.0 / (sqrt(var) + 1e-7));
    const float fm = (float)mean;

    const float4* y4 = ((const float4*)y) + (long long)b * (SS * DD / 4);
    __half2* yh2 = ((__half2*)yh) + (long long)b * (SS * DD / 2);
    const long long i = (long long)blockIdx.x * 256 + threadIdx.x;  // grid.x = 2048
    float4 vv = y4[i];
    vv.x = (vv.x - fm) * inv; vv.y = (vv.y - fm) * inv;
    vv.z = (vv.z - fm) * inv; vv.w = (vv.w - fm) * inv;
    yh2[i * 2]     = __floats2half2_rn(vv.x, vv.y);
    yh2[i * 2 + 1] = __floats2half2_rn(vv.z, vv.w);
}

// out[b,d,s] = (y2[b,s,d] - mean) * inv
__global__ void apply2t_kernel(const float* __restrict__ y2, float* __restrict__ out)
{
    const int b = blockIdx.z;
    const double sum = g_acc[16 + 2 * b], sq = g_acc[16 + 2 * b + 1];
    const double NE = (double)SS * DD;
    const double mean = sum / NE;
    double var = sq - NE * mean * mean;
    if (var < 0.0) var = 0.0;
    const float inv = (float)(1.0 / (sqrt(var) + 1e-7));
    const float fm = (float)mean;

    const int s0 = blockIdx.x * 32;
    const int d0 = blockIdx.y * 32;
    __shared__ float ys[32][33];
    const int tx = threadIdx.x, ty = threadIdx.y;

#pragma unroll
    for (int i = 0; i < 32; i += 8)
        ys[ty + i][tx] = y2[((long long)b * SS + s0 + ty + i) * DD + d0 + tx];
    __syncthreads();
#pragma unroll
    for (int i = 0; i < 32; i += 8)
        out[((long long)b * DD + d0 + ty + i) * SS + s0 + tx] =
            (ys[tx][ty + i] - fm) * inv;
}

// ---------------- host-side orchestration ----------------
template <typename T>
static T* sym(const void* symbol)
{
    void* p = nullptr;
    cudaGetSymbolAddress(&p, symbol);
    return (T*)p;
}

extern "C" void kernel_launch(void* const* d_in, const int* in_sizes, int n_in,
                              void* d_out, int out_size)
{
    const float* x  = (const float*)d_in[0];
    const float* Wq = (const float*)d_in[1];
    const float* Wk = (const float*)d_in[2];
    const float* Wv = (const float*)d_in[3];
    const float* Wo = (const float*)d_in[4];
    const float* W1 = (const float*)d_in[5];
    const float* b1 = (const float*)d_in[6];
    const float* W2 = (const float*)d_in[7];
    const float* b2 = (const float*)d_in[8];
    float* out = (float*)d_out;

    float*  py    = sym<float>((const void*)g_y);
    float*  ph2   = sym<float>((const void*)g_h2);
    float*  prs   = sym<float>((const void*)g_rowsum);
    double* pacc  = sym<double>((const void*)g_acc);
    __half* pxh   = sym<__half>((const void*)g_xh);
    __half* pqkh  = sym<__half>((const void*)g_qkh);
    __half* pvt   = sym<__half>((const void*)g_vt);
    __half* psh   = sym<__half>((const void*)g_sh);
    __half* pyh   = sym<__half>((const void*)g_yh);
    __half* ph1h  = sym<__half>((const void*)g_h1h);
    __half* pwqkT = sym<__half>((const void*)g_wqkT);
    __half* pwvh  = sym<__half>((const void*)g_wvh);
    __half* pwoT  = sym<__half>((const void*)g_woT);
    __half* pwvoT = sym<__half>((const void*)g_wvoT);
    __half* pw1T  = sym<__half>((const void*)g_w1T);
    __half* pw2T  = sym<__half>((const void*)g_w2T);

    const long long sSD  = (long long)SS * DD;
    const long long sS2D = (long long)SS * 2 * DD;
    const long long sSS  = (long long)SS * SS;
    const long long sSF  = (long long)SS * FF;
    const long long sDS  = (long long)DD * SS;

    cudaFuncSetAttribute(gemm_h<0, 1>, cudaFuncAttributeMaxDynamicSharedMemorySize, SMEMB);
    cudaFuncSetAttribute(gemm_h<0, 2>, cudaFuncAttributeMaxDynamicSharedMemorySize, SMEMB);
    cudaFuncSetAttribute(gemm_h<2, 1>, cudaFuncAttributeMaxDynamicSharedMemorySize, SMEMB);
    cudaFuncSetAttribute(gemm_h<3, 0>, cudaFuncAttributeMaxDynamicSharedMemorySize, SMEMB);
    cudaFuncSetAttribute(gemm_h<4, 0>, cudaFuncAttributeMaxDynamicSharedMemorySize, SMEMB);
    cudaFuncSetAttribute(gemm_h<5, 1>, cudaFuncAttributeMaxDynamicSharedMemorySize, SMEMB);

    // static side streams + events (created once, outside any capture)
    static cudaStream_t s1 = nullptr, s2 = nullptr;
    static cudaEvent_t evFork = nullptr, evX = nullptr, evV = nullptr, evW = nullptr;
    if (s1 == nullptr) {
        cudaStreamCreateWithFlags(&s1, cudaStreamNonBlocking);
        cudaStreamCreateWithFlags(&s2, cudaStreamNonBlocking);
        cudaEventCreateWithFlags(&evFork, cudaEventDisableTiming);
        cudaEventCreateWithFlags(&evX, cudaEventDisableTiming);
        cudaEventCreateWithFlags(&evV, cudaEventDisableTiming);
        cudaEventCreateWithFlags(&evW, cudaEventDisableTiming);
    }

    dim3 tblk(32, 8);
    dim3 blk(128);
    dim3 gW(DD / 128, DD / 128, 1);          // (4,4,1) weight-product GEMM
    dim3 gQK(2 * DD / 128, SS / 128, BB);    // (8,32,8) merged q|k projection
    dim3 gNarrow(DD / 128, SS / 128, BB);    // (4,32,8)
    dim3 gScore(SS / 128, SS / 128, BB);     // (32,32,8)
    dim3 gFFN(FF / 128, SS / 128, BB);       // (16,32,8)

    // ---- main stream: zero + x transpose + q/k weights ----
    zero_all_kernel<<<BB * SS / 256, 256>>>(prs);
    cudaEventRecord(evFork, 0);              // fork point for W1/W2 branch

    transpose_h<<<dim3(SS / 32, DD / 32, BB), tblk>>>(x, pxh, DD, SS);
    cudaEventRecord(evX, 0);                 // xh ready (for v' branch)

    transpose_h<<<dim3(DD / 32, DD / 32, 1), tblk>>>(Wq, pwqkT,           DD, DD);
    transpose_h<<<dim3(DD / 32, DD / 32, 1), tblk>>>(Wk, pwqkT + DD * DD, DD, DD);

    // ---- side stream s1: Wo/Wv prep, WvWo product, v' projection ----
    cudaStreamWaitEvent(s1, evX, 0);
    transpose_h<<<dim3(DD / 32, DD / 32, 1), tblk, 0, s1>>>(Wo, pwoT, DD, DD);
    convert_h<<<DD * DD / 1024, 256, 0, s1>>>(Wv, pwvh);
    gemm_h<0, 1><<<gW, blk, SMEMB, s1>>>(pwoT, pwvh, nullptr, pwvoT,
        DD, DD, DD, DD, 0, 0, 0, nullptr, 0, nullptr, nullptr, nullptr, 0.f);
    gemm_h<0, 2><<<gNarrow, blk, SMEMB, s1>>>(pxh, pwvoT, nullptr, pvt,
        DD, DD, DD, SS, sSD, 0, sDS, nullptr, 0, nullptr, nullptr, nullptr, 0.f);
    cudaEventRecord(evV, s1);

    // ---- side stream s2: FFN weight transposes ----
    cudaStreamWaitEvent(s2, evFork, 0);
    transpose_h<<<dim3(FF / 32, DD / 32, 1), tblk, 0, s2>>>(W1, pw1T, DD, FF);
    transpose_h<<<dim3(DD / 32, FF / 32, 1), tblk, 0, s2>>>(W2, pw2T, FF, DD);
    cudaEventRecord(evW, s2);

    // ---- main stream: attention chain ----
    // qk = xh @ [WqT|WkT]^T  (fp16 out, N=1024 merged)
    gemm_h<0, 1><<<gQK, blk, SMEMB>>>(pxh, pwqkT, nullptr, pqkh,
        DD, DD, DD, 2 * DD, sSD, 0, sS2D, nullptr, 0, nullptr, nullptr, nullptr, 0.f);

    // e = 2^(q @ k^T * scale*log2e)  (fp16 out, row sums into g_rowsum)
    gemm_h<5, 1><<<gScore, blk, SMEMB>>>(pqkh, pqkh + DD, nullptr, psh,
        DD, 2 * DD, 2 * DD, SS, sS2D, sS2D, sSS, nullptr, 0, nullptr, nullptr,
        prs, 0.06375810406f /* log2(e)/sqrt(512) */);

    // join v' branch, then AV GEMM
    cudaStreamWaitEvent(0, evV, 0);
    // y = (e @ v') / rowsum + x^T  (fused normalize + residual + stats stage 0)
    gemm_h<3, 0><<<gNarrow, blk, SMEMB>>>(psh, pvt, nullptr, py,
        SS, SS, SS, DD, sSS, sDS, sSD, x, sDS, pacc, nullptr, prs, 0.f);

    apply1h_kernel<<<dim3(2048, BB), 256>>>(py, pyh);

    // join W1/W2 branch, then FFN
    cudaStreamWaitEvent(0, evW, 0);
    gemm_h<2, 1><<<gFFN, blk, SMEMB>>>(pyh, pw1T, b1, ph1h,
        DD, DD, DD, FF, sSD, 0, sSF, nullptr, 0, nullptr, nullptr, nullptr, 0.f);
    // h2 = h1 @ W2 + b2 + normalize(y)  (fused residual + stats stage 1, fp32 out)
    gemm_h<4, 0><<<gNarrow, blk, SMEMB>>>(ph1h, pw2T, b2, ph2,
        FF, FF, FF, DD, sSF, 0, sSD, py, sSD, pacc + 16, pacc, nullptr, 0.f);

    apply2t_kernel<<<dim3(SS / 32, DD / 32, BB), tblk>>>(ph2, out);

    (void)in_sizes; (void)n_in; (void)out_size;
}